// round 5
// baseline (speedup 1.0000x reference)
#include <cuda_runtime.h>

typedef unsigned long long ull;

// ---------------------------------------------------------------------------
// Forecaster_PONI round 5: vertical-pair FFMA2 convs with FIXED per-sub-block
// smem slices for intra-block split-K (R4's tile-aliasing bug corrected).
// ---------------------------------------------------------------------------

__device__ __forceinline__ float lrelu_f(float v) { return v > 0.f ? v : 0.2f * v; }
__device__ __forceinline__ float sigm_f(float v)  { return 1.f / (1.f + __expf(-v)); }

__device__ __forceinline__ void upk(ull v, float& a, float& b) {
    asm("mov.b64 {%0,%1}, %2;" : "=f"(a), "=f"(b) : "l"(v));
}
__device__ __forceinline__ void fma2(ull& d, ull a, ull b) {
    asm("fma.rn.f32x2 %0, %1, %2, %0;" : "+l"(d) : "l"(a), "l"(b));
}
__device__ __forceinline__ ull add2(ull a, ull b) {
    ull r;
    asm("add.rn.f32x2 %0, %1, %2;" : "=l"(r) : "l"(a), "l"(b));
    return r;
}

// ------------------------------ scratch buffers ----------------------------
__device__ float g_e1[160 * 16 * 96 * 96];
__device__ float g_e2[160 * 64 * 48 * 48];
__device__ float g_e3[160 * 96 * 24 * 24];
__device__ float g_c3[2][16 * 96 * 24 * 24];
__device__ float g_c2[2][16 * 64 * 48 * 48];
__device__ float g_c1[2][16 * 16 * 96 * 96];
__device__ float g_g3[16 * 192 * 24 * 24];
__device__ float g_g2[16 * 128 * 48 * 48];
__device__ float g_g1[16 * 32 * 96 * 96];
__device__ float g_o3[16 * 64 * 48 * 48];
__device__ float g_o2[16 * 16 * 96 * 96];
__device__ float g_o1[16 * 8 * 192 * 192];

// ---------------------------------------------------------------------------
// conv3x3_v5: stride-1 SAME conv over [x1 (C1) ++ x2 (C2)].
// Thread computes an output ROW-PAIR (2 rows) x 4 cols x COT channels.
// smem holds row-pairs P(r) = (in[r], in[r+1]) as float2 -> every tap is one
// LDS.64 feeding fma.rn.f32x2 directly (lanes = the two output rows).
// KS-way intra-block split over input channels. Each sub-block ks owns smem
// channel slice [ks*CICH, (ks+1)*CICH) of a CHT = KS*CICH channel tile.
// MODE 1 = gate conv (ACT 2 sigmoid). MODE 2 = GRU candidate: x2 scaled by r
// on load, epilogue out = (1-z)*h + z*lrelu(acc+b).
// ---------------------------------------------------------------------------
template<int C1, int C2, int CO, int H, int W, int ACT, int MODE,
         int TY, int TX, int CICH, int COT, int KS>
__global__ void __launch_bounds__(KS * (TY / 2) * (TX / 4))
conv3x3_v5(const float* __restrict__ x1, const float* __restrict__ x2,
           const float* __restrict__ gates, const float* __restrict__ wgt,
           const float* __restrict__ bias, float* __restrict__ out)
{
    constexpr int CI  = C1 + C2;
    constexpr int CIP = CI / KS;
    constexpr int CHT = KS * CICH;
    constexpr int SH1 = TY + 1, SW = TX + 2;
    constexpr int NTS = (TY / 2) * (TX / 4);
    constexpr int NT  = KS * NTS;
    constexpr int TXT = W / TX;
    constexpr size_t B_P2  = (size_t)CHT * SH1 * SW * 8;
    constexpr size_t B_RED = (KS > 1) ? (size_t)(KS / 2) * NTS * COT * 4 * 8 : 8;
    constexpr size_t B_A   = (B_P2 > B_RED ? B_P2 : B_RED);

    __shared__ __align__(16) char   s_raw[B_A];
    __shared__ __align__(16) float2 s_w[CHT][COT][3][4];
    float2* s_p2  = (float2*)s_raw;   // [CHT][SH1][SW]
    ull*    s_red = (ull*)s_raw;

    const int n   = blockIdx.z;
    const int cob = blockIdx.y * COT;
    const int ty0 = (blockIdx.x / TXT) * TY;
    const int tx0 = (blockIdx.x % TXT) * TX;
    const int tid = threadIdx.x;
    const int ks  = tid / NTS;
    const int lid = tid - ks * NTS;
    const int lx  = lid % (TX / 4);
    const int ly  = lid / (TX / 4);

    ull acc[COT][4];
#pragma unroll
    for (int c = 0; c < COT; c++)
#pragma unroll
        for (int x = 0; x < 4; x++) acc[c][x] = 0ULL;

    for (int ci0 = 0; ci0 < CIP; ci0 += CICH) {
        // cooperative load: CHT channels; channel c belongs to slice c/CICH
        for (int idx = tid; idx < CHT * SH1 * SW; idx += NT) {
            int c   = idx / (SH1 * SW);
            int rem = idx - c * (SH1 * SW);
            int pr  = rem / SW;
            int xx  = rem - pr * SW;
            int gy = ty0 - 1 + pr, gx = tx0 - 1 + xx;
            int ci = (c / CICH) * CIP + ci0 + (c % CICH);
            float v0 = 0.f, v1 = 0.f;
            if ((unsigned)gx < (unsigned)W) {
                if (ci < C1) {
                    const float* p = x1 + (((size_t)n * C1 + ci) * H) * W + gx;
                    if ((unsigned)gy < (unsigned)H)       v0 = p[(size_t)gy * W];
                    if ((unsigned)(gy + 1) < (unsigned)H) v1 = p[(size_t)(gy + 1) * W];
                } else {
                    int c2 = ci - C1;
                    const float* p = x2 + (((size_t)n * C2 + c2) * H) * W + gx;
                    if ((unsigned)gy < (unsigned)H) {
                        v0 = p[(size_t)gy * W];
                        if (MODE == 2)
                            v0 *= gates[(((size_t)n * 2 * C2 + C2 + c2) * H + gy) * W + gx];
                    }
                    if ((unsigned)(gy + 1) < (unsigned)H) {
                        v1 = p[(size_t)(gy + 1) * W];
                        if (MODE == 2)
                            v1 *= gates[(((size_t)n * 2 * C2 + C2 + c2) * H + gy + 1) * W + gx];
                    }
                }
            }
            s_p2[((size_t)c * SH1 + pr) * SW + xx] = make_float2(v0, v1);
        }
        for (int idx = tid; idx < CHT * COT * 9; idx += NT) {
            int c   = idx / (COT * 9);
            int rem = idx - c * (COT * 9);
            int co  = rem / 9;
            int k   = rem - co * 9;
            int ci  = (c / CICH) * CIP + ci0 + (c % CICH);
            float v = wgt[((cob + co) * CI + ci) * 9 + k];
            s_w[c][co][k / 3][k % 3] = make_float2(v, v);
        }
        __syncthreads();

        const int cbase = ks * CICH;
        for (int cc = 0; cc < CICH; cc++) {
            const int c = cbase + cc;
#pragma unroll
            for (int ky = 0; ky < 3; ky++) {
                const ull* row = (const ull*)&s_p2[((size_t)c * SH1 + (2 * ly + ky)) * SW + 4 * lx];
                ull P[6];
#pragma unroll
                for (int x = 0; x < 6; x++) P[x] = row[x];
#pragma unroll
                for (int co = 0; co < COT; co++) {
                    ulonglong2 wa = *(const ulonglong2*)&s_w[c][co][ky][0];
                    ull        wc = *(const ull*)&s_w[c][co][ky][2];
                    ull wk[3] = {wa.x, wa.y, wc};
#pragma unroll
                    for (int x = 0; x < 4; x++)
#pragma unroll
                        for (int kx = 0; kx < 3; kx++)
                            fma2(acc[co][x], P[x + kx], wk[kx]);
                }
            }
        }
        __syncthreads();
    }

    if (KS > 1) {
        for (int step = KS / 2; step >= 1; step >>= 1) {
            if (ks >= step && ks < 2 * step) {
                ull* dst = &s_red[((size_t)(ks - step) * NTS + lid) * COT * 4];
#pragma unroll
                for (int c = 0; c < COT; c++)
#pragma unroll
                    for (int x = 0; x < 4; x++) dst[c * 4 + x] = acc[c][x];
            }
            __syncthreads();
            if (ks < step) {
                const ull* src = &s_red[((size_t)ks * NTS + lid) * COT * 4];
#pragma unroll
                for (int c = 0; c < COT; c++)
#pragma unroll
                    for (int x = 0; x < 4; x++) acc[c][x] = add2(acc[c][x], src[c * 4 + x]);
            }
            __syncthreads();
        }
    }

    if (ks != 0) return;

    const int oy = ty0 + 2 * ly, ox = tx0 + 4 * lx;
#pragma unroll
    for (int co = 0; co < COT; co++) {
        float bv = bias[cob + co];
        float lo[4], hi[4];
#pragma unroll
        for (int x = 0; x < 4; x++) {
            float a, b;
            upk(acc[co][x], a, b);
            a += bv; b += bv;
            if (ACT == 1) { a = lrelu_f(a); b = lrelu_f(b); }
            if (ACT == 2) { a = sigm_f(a);  b = sigm_f(b); }
            lo[x] = a; hi[x] = b;
        }
        size_t off0 = (((size_t)n * CO + cob + co) * H + oy) * W + ox;
        size_t off1 = off0 + W;
        if (MODE == 2) {
            size_t goff = (((size_t)n * 2 * CO + cob + co) * H + oy) * W + ox;
            float4 z0 = *(const float4*)&gates[goff];
            float4 z1 = *(const float4*)&gates[goff + W];
            float4 h0 = *(const float4*)&x2[off0];
            float4 h1 = *(const float4*)&x2[off1];
            lo[0] = (1.f - z0.x) * h0.x + z0.x * lo[0];
            lo[1] = (1.f - z0.y) * h0.y + z0.y * lo[1];
            lo[2] = (1.f - z0.z) * h0.z + z0.z * lo[2];
            lo[3] = (1.f - z0.w) * h0.w + z0.w * lo[3];
            hi[0] = (1.f - z1.x) * h1.x + z1.x * hi[0];
            hi[1] = (1.f - z1.y) * h1.y + z1.y * hi[1];
            hi[2] = (1.f - z1.z) * h1.z + z1.z * hi[2];
            hi[3] = (1.f - z1.w) * h1.w + z1.w * hi[3];
        }
        float4 v0 = {lo[0], lo[1], lo[2], lo[3]};
        float4 v1 = {hi[0], hi[1], hi[2], hi[3]};
        *(float4*)&out[off0] = v0;
        *(float4*)&out[off1] = v1;
    }
}

// ---------------------------------------------------------------------------
// deconv_v5: 4x4 stride-2 SAME transposed conv (unflipped kernel):
// out(2i+dy, 2j+dx) = sum_{a,b} in[i-1+a+dy][j-1+b+dx] * w[dy+2a][dx+2b]
// Thread owns a 2x2 input patch -> 4x4 outputs. Vertical output pairs (dy=0/1)
// use smem row-pairs P(r)=(in[r],in[r+1]) and weight pairs
// (w[2a][k], w[2a+1][k]). KS split-K with per-sub-block smem slices.
// ---------------------------------------------------------------------------
template<int CI, int CO, int HIN, int TY, int TX, int CICH, int COT, int KS>
__global__ void __launch_bounds__(KS * (TY / 2) * (TX / 2))
deconv_v5(const float* __restrict__ x, const float* __restrict__ wgt,
          const float* __restrict__ bias, float* __restrict__ out)
{
    constexpr int WIN = HIN, HO = 2 * HIN, WO = 2 * HIN;
    constexpr int CIP = CI / KS;
    constexpr int CHT = KS * CICH;
    constexpr int SH1 = TY + 1, SW = TX + 2;
    constexpr int NTS = (TY / 2) * (TX / 2);
    constexpr int NT  = KS * NTS;
    constexpr int TXT = WIN / TX;
    constexpr size_t B_P2  = (size_t)CHT * SH1 * SW * 8;
    constexpr size_t B_RED = (KS > 1) ? (size_t)(KS / 2) * NTS * COT * 8 * 8 : 8;
    constexpr size_t B_A   = (B_P2 > B_RED ? B_P2 : B_RED);

    __shared__ __align__(16) char   s_raw[B_A];
    __shared__ __align__(16) float2 s_wd[CHT][COT][2][4];
    float2* s_p2  = (float2*)s_raw;
    ull*    s_red = (ull*)s_raw;

    const int n   = blockIdx.z;
    const int cob = blockIdx.y * COT;
    const int ty0 = (blockIdx.x / TXT) * TY;
    const int tx0 = (blockIdx.x % TXT) * TX;
    const int tid = threadIdx.x;
    const int ks  = tid / NTS;
    const int lid = tid - ks * NTS;
    const int lx  = lid % (TX / 2);
    const int ly  = lid / (TX / 2);

    ull acc[COT][2][4];
#pragma unroll
    for (int c = 0; c < COT; c++)
#pragma unroll
        for (int u = 0; u < 2; u++)
#pragma unroll
            for (int v = 0; v < 4; v++) acc[c][u][v] = 0ULL;

    for (int ci0 = 0; ci0 < CIP; ci0 += CICH) {
        for (int idx = tid; idx < CHT * SH1 * SW; idx += NT) {
            int c   = idx / (SH1 * SW);
            int rem = idx - c * (SH1 * SW);
            int pr  = rem / SW;
            int xx  = rem - pr * SW;
            int gy = ty0 - 1 + pr, gx = tx0 - 1 + xx;
            int ci = (c / CICH) * CIP + ci0 + (c % CICH);
            float v0 = 0.f, v1 = 0.f;
            if ((unsigned)gx < (unsigned)WIN) {
                const float* p = x + (((size_t)n * CI + ci) * HIN) * WIN + gx;
                if ((unsigned)gy < (unsigned)HIN)       v0 = p[(size_t)gy * WIN];
                if ((unsigned)(gy + 1) < (unsigned)HIN) v1 = p[(size_t)(gy + 1) * WIN];
            }
            s_p2[((size_t)c * SH1 + pr) * SW + xx] = make_float2(v0, v1);
        }
        for (int idx = tid; idx < CHT * COT * 8; idx += NT) {
            int c   = idx / (COT * 8);
            int rem = idx - c * (COT * 8);
            int co  = rem / 8;
            int ak  = rem - co * 8;
            int a = ak / 4, k = ak - a * 4;
            int ci = (c / CICH) * CIP + ci0 + (c % CICH);
            const float* wp = wgt + ((size_t)(cob + co) * CI + ci) * 16;
            s_wd[c][co][a][k] = make_float2(wp[(2 * a) * 4 + k], wp[(2 * a + 1) * 4 + k]);
        }
        __syncthreads();

        const int cbase = ks * CICH;
        for (int cc = 0; cc < CICH; cc++) {
            const int c = cbase + cc;
            ull P[3][4];
#pragma unroll
            for (int dr = 0; dr < 3; dr++) {
                const ull* row = (const ull*)&s_p2[((size_t)c * SH1 + (2 * ly + dr)) * SW + 2 * lx];
#pragma unroll
                for (int xx = 0; xx < 4; xx++) P[dr][xx] = row[xx];
            }
#pragma unroll
            for (int co = 0; co < COT; co++) {
                ulonglong2 wa0 = *(const ulonglong2*)&s_wd[c][co][0][0];
                ulonglong2 wa1 = *(const ulonglong2*)&s_wd[c][co][0][2];
                ulonglong2 wb0 = *(const ulonglong2*)&s_wd[c][co][1][0];
                ulonglong2 wb1 = *(const ulonglong2*)&s_wd[c][co][1][2];
                ull wk[2][4] = {{wa0.x, wa0.y, wa1.x, wa1.y},
                                {wb0.x, wb0.y, wb1.x, wb1.y}};
#pragma unroll
                for (int u = 0; u < 2; u++)
#pragma unroll
                    for (int v = 0; v < 4; v++)
#pragma unroll
                        for (int a = 0; a < 2; a++)
#pragma unroll
                            for (int b = 0; b < 2; b++)
                                fma2(acc[co][u][v],
                                     P[u + a][(v >> 1) + (v & 1) + b],
                                     wk[a][(v & 1) + 2 * b]);
            }
        }
        __syncthreads();
    }

    if (KS > 1) {
        for (int step = KS / 2; step >= 1; step >>= 1) {
            if (ks >= step && ks < 2 * step) {
                ull* dst = &s_red[((size_t)(ks - step) * NTS + lid) * COT * 8];
#pragma unroll
                for (int c = 0; c < COT; c++)
#pragma unroll
                    for (int u = 0; u < 2; u++)
#pragma unroll
                        for (int v = 0; v < 4; v++) dst[(c * 2 + u) * 4 + v] = acc[c][u][v];
            }
            __syncthreads();
            if (ks < step) {
                const ull* src = &s_red[((size_t)ks * NTS + lid) * COT * 8];
#pragma unroll
                for (int c = 0; c < COT; c++)
#pragma unroll
                    for (int u = 0; u < 2; u++)
#pragma unroll
                        for (int v = 0; v < 4; v++)
                            acc[c][u][v] = add2(acc[c][u][v], src[(c * 2 + u) * 4 + v]);
            }
            __syncthreads();
        }
    }

    if (ks != 0) return;

    const int iy = ty0 + 2 * ly, jx = tx0 + 2 * lx;
#pragma unroll
    for (int co = 0; co < COT; co++) {
        float bv = bias[cob + co];
#pragma unroll
        for (int u = 0; u < 2; u++) {
            float lo[4], hi[4];
#pragma unroll
            for (int v = 0; v < 4; v++) {
                float a, b;
                upk(acc[co][u][v], a, b);
                lo[v] = lrelu_f(a + bv);
                hi[v] = lrelu_f(b + bv);
            }
            int orow = 2 * (iy + u);
            int ocol = 2 * jx;
            float4 v0 = {lo[0], lo[1], lo[2], lo[3]};
            float4 v1 = {hi[0], hi[1], hi[2], hi[3]};
            *(float4*)&out[(((size_t)n * CO + cob + co) * HO + orow) * WO + ocol]     = v0;
            *(float4*)&out[(((size_t)n * CO + cob + co) * HO + orow + 1) * WO + ocol] = v1;
        }
    }
}

// ---------------------------------------------------------------------------
// Encoder: 3x3 stride-2 SAME conv. pad_lo = 0: out[y] uses in[2y + ky].
// REMAP folds [B,T]->[T,B] transpose into enc1's read.
// ---------------------------------------------------------------------------
template<int CI, int CO, int HIN, bool REMAP, int TY, int TX, int CICH, int COT>
__global__ void __launch_bounds__(TY * TX)
conv3x3s2_k(const float* __restrict__ x, const float* __restrict__ wgt,
            const float* __restrict__ bias, float* __restrict__ out)
{
    constexpr int WIN = HIN, HO = HIN / 2, WO = HIN / 2;
    constexpr int SH = 2 * TY + 1, SW = 2 * TX + 1;
    constexpr int NT = TY * TX;
    constexpr int TILES_X = (WO + TX - 1) / TX;
    __shared__ float s_in[CICH][SH][SW];
    __shared__ float s_w[CICH][COT][9];

    const int n   = blockIdx.z;
    const int cob = blockIdx.y * COT;
    const int ty0 = (blockIdx.x / TILES_X) * TY;
    const int tx0 = (blockIdx.x % TILES_X) * TX;
    const int tid = threadIdx.x;
    const int lx  = tid % TX;
    const int ly  = tid / TX;

    float acc[COT];
#pragma unroll
    for (int c = 0; c < COT; c++) acc[c] = 0.f;

    for (int ci0 = 0; ci0 < CI; ci0 += CICH) {
        for (int idx = tid; idx < CICH * SH * SW; idx += NT) {
            int c   = idx / (SH * SW);
            int rem = idx - c * (SH * SW);
            int iy  = rem / SW;
            int ix  = rem - iy * SW;
            int gy = 2 * ty0 + iy, gx = 2 * tx0 + ix;
            int ci = ci0 + c;
            float v = 0.f;
            if (gy < HIN && gx < WIN) {
                int frame = REMAP ? ((n % 16) * 10 + n / 16) : n;
                v = x[(((size_t)frame * CI + ci) * HIN + gy) * WIN + gx];
            }
            s_in[c][iy][ix] = v;
        }
        for (int idx = tid; idx < CICH * COT * 9; idx += NT) {
            int c   = idx / (COT * 9);
            int rem = idx - c * (COT * 9);
            int co  = rem / 9;
            int k   = rem - co * 9;
            s_w[c][co][k] = wgt[((cob + co) * CI + (ci0 + c)) * 9 + k];
        }
        __syncthreads();

        for (int c = 0; c < CICH; c++) {
            float p[3][3];
#pragma unroll
            for (int r = 0; r < 3; r++)
#pragma unroll
                for (int cc = 0; cc < 3; cc++)
                    p[r][cc] = s_in[c][2 * ly + r][2 * lx + cc];
#pragma unroll
            for (int co = 0; co < COT; co++) {
#pragma unroll
                for (int k = 0; k < 9; k++)
                    acc[co] = fmaf(p[k / 3][k % 3], s_w[c][co][k], acc[co]);
            }
        }
        __syncthreads();
    }

    const int oy = ty0 + ly, ox = tx0 + lx;
    if (oy < HO && ox < WO) {
#pragma unroll
        for (int co = 0; co < COT; co++) {
            float v = lrelu_f(acc[co] + bias[cob + co]);
            out[(((size_t)n * CO + cob + co) * HO + oy) * WO + ox] = v;
        }
    }
}

// ---------------------------------------------------------------------------
// Head: 3x3 conv, 8 -> 1 channels, 192x192.
// ---------------------------------------------------------------------------
__global__ void head_k(const float* __restrict__ x, const float* __restrict__ w,
                       const float* __restrict__ b, float* __restrict__ out)
{
    __shared__ float sw[72];
    __shared__ float sb;
    if (threadIdx.x < 72) sw[threadIdx.x] = w[threadIdx.x];
    if (threadIdx.x == 0) sb = b[0];
    __syncthreads();

    const int HW = 192 * 192;
    int idx = blockIdx.x * blockDim.x + threadIdx.x;
    if (idx >= 16 * HW) return;
    int n   = idx / HW;
    int rem = idx - n * HW;
    int y   = rem / 192;
    int xq  = rem - y * 192;

    float acc = sb;
#pragma unroll
    for (int ci = 0; ci < 8; ci++) {
        const float* xp = x + (size_t)(n * 8 + ci) * HW;
#pragma unroll
        for (int ky = 0; ky < 3; ky++) {
            int yy = y + ky - 1;
            if ((unsigned)yy >= 192u) continue;
#pragma unroll
            for (int kx = 0; kx < 3; kx++) {
                int xx = xq + kx - 1;
                if ((unsigned)xx >= 192u) continue;
                acc = fmaf(xp[yy * 192 + xx], sw[ci * 9 + ky * 3 + kx], acc);
            }
        }
    }
    out[idx] = acc;
}

// ---------------------------------------------------------------------------
// host
// ---------------------------------------------------------------------------
extern "C" void kernel_launch(void* const* d_in, const int* in_sizes, int n_in,
                              void* d_out, int out_size)
{
    const float* h1     = (const float*)d_in[0];
    const float* h2     = (const float*)d_in[1];
    const float* h3     = (const float*)d_in[2];
    const float* y_add  = (const float*)d_in[3];
    const float* enc_w1 = (const float*)d_in[4];
    const float* enc_b1 = (const float*)d_in[5];
    const float* enc_w2 = (const float*)d_in[6];
    const float* enc_b2 = (const float*)d_in[7];
    const float* enc_w3 = (const float*)d_in[8];
    const float* enc_b3 = (const float*)d_in[9];
    const float* g3wg   = (const float*)d_in[10];
    const float* g3bg   = (const float*)d_in[11];
    const float* g3wc   = (const float*)d_in[12];
    const float* g3bc   = (const float*)d_in[13];
    const float* g2wg   = (const float*)d_in[14];
    const float* g2bg   = (const float*)d_in[15];
    const float* g2wc   = (const float*)d_in[16];
    const float* g2bc   = (const float*)d_in[17];
    const float* g1wg   = (const float*)d_in[18];
    const float* g1bg   = (const float*)d_in[19];
    const float* g1wc   = (const float*)d_in[20];
    const float* g1bc   = (const float*)d_in[21];
    const float* s3w    = (const float*)d_in[22];
    const float* s3b    = (const float*)d_in[23];
    const float* s2w    = (const float*)d_in[24];
    const float* s2b    = (const float*)d_in[25];
    const float* s1w    = (const float*)d_in[26];
    const float* s1b    = (const float*)d_in[27];
    const float* hw     = (const float*)d_in[28];
    const float* hb     = (const float*)d_in[29];
    float* out = (float*)d_out;

    float *e1, *e2, *e3, *c3b, *c2b, *c1b, *gg3, *gg2, *gg1, *o3, *o2, *o1;
    cudaGetSymbolAddress((void**)&e1, g_e1);
    cudaGetSymbolAddress((void**)&e2, g_e2);
    cudaGetSymbolAddress((void**)&e3, g_e3);
    cudaGetSymbolAddress((void**)&c3b, g_c3);
    cudaGetSymbolAddress((void**)&c2b, g_c2);
    cudaGetSymbolAddress((void**)&c1b, g_c1);
    cudaGetSymbolAddress((void**)&gg3, g_g3);
    cudaGetSymbolAddress((void**)&gg2, g_g2);
    cudaGetSymbolAddress((void**)&gg1, g_g1);
    cudaGetSymbolAddress((void**)&o3, g_o3);
    cudaGetSymbolAddress((void**)&o2, g_o2);
    cudaGetSymbolAddress((void**)&o1, g_o1);

    const size_t SZ3 = (size_t)16 * 96 * 24 * 24;
    const size_t SZ2 = (size_t)16 * 64 * 48 * 48;
    const size_t SZ1 = (size_t)16 * 16 * 96 * 96;

    // -------- encoder over all 160 frames (transpose folded into enc1) -----
    conv3x3s2_k<1, 16, 192, true, 16, 16, 1, 16><<<dim3(36, 1, 160), 256>>>(
        y_add, enc_w1, enc_b1, e1);
    conv3x3s2_k<16, 64, 96, false, 16, 16, 8, 8><<<dim3(9, 8, 160), 256>>>(
        e1, enc_w2, enc_b2, e2);
    conv3x3s2_k<64, 96, 48, false, 16, 16, 8, 8><<<dim3(4, 12, 160), 256>>>(
        e2, enc_w3, enc_b3, e3);

    cudaMemcpyAsync(c3b, h3, SZ3 * sizeof(float), cudaMemcpyDeviceToDevice);
    cudaMemcpyAsync(c2b, h2, SZ2 * sizeof(float), cudaMemcpyDeviceToDevice);
    cudaMemcpyAsync(c1b, h1, SZ1 * sizeof(float), cudaMemcpyDeviceToDevice);

    for (int t = 0; t < 10; t++) {
        const float* x3 = e3 + (size_t)t * 16 * 96 * 24 * 24;
        float* c3c = c3b + (size_t)(t & 1) * SZ3;
        float* c3n = c3b + (size_t)((t + 1) & 1) * SZ3;
        float* c2c = c2b + (size_t)(t & 1) * SZ2;
        float* c2n = c2b + (size_t)((t + 1) & 1) * SZ2;
        float* c1c = c1b + (size_t)(t & 1) * SZ1;
        float* c1n = c1b + (size_t)((t + 1) & 1) * SZ1;

        // --- level 3 (24x24, 96 ch) ---
        conv3x3_v5<96, 96, 192, 24, 24, 2, 1, 24, 24, 2, 8, 4>
            <<<dim3(1, 24, 16), 288>>>(x3, c3c, nullptr, g3wg, g3bg, gg3);
        conv3x3_v5<96, 96, 96, 24, 24, 1, 2, 24, 24, 2, 4, 4>
            <<<dim3(1, 24, 16), 288>>>(x3, c3c, gg3, g3wc, g3bc, c3n);
        deconv_v5<96, 64, 24, 24, 24, 4, 4, 2>
            <<<dim3(1, 16, 16), 288>>>(c3n, s3w, s3b, o3);

        // --- level 2 (48x48, 64 ch) ---
        conv3x3_v5<64, 64, 128, 48, 48, 2, 1, 24, 48, 2, 8, 2>
            <<<dim3(2, 16, 16), 288>>>(o3, c2c, nullptr, g2wg, g2bg, gg2);
        conv3x3_v5<64, 64, 64, 48, 48, 1, 2, 24, 48, 2, 8, 2>
            <<<dim3(2, 8, 16), 288>>>(o3, c2c, gg2, g2wc, g2bc, c2n);
        deconv_v5<64, 16, 48, 12, 48, 8, 4, 1>
            <<<dim3(4, 4, 16), 144>>>(c2n, s2w, s2b, o2);

        // --- level 1 (96x96, 16 ch) ---
        conv3x3_v5<16, 16, 32, 96, 96, 2, 1, 24, 48, 4, 4, 1>
            <<<dim3(8, 8, 16), 144>>>(o2, c1c, nullptr, g1wg, g1bg, gg1);
        conv3x3_v5<16, 16, 16, 96, 96, 1, 2, 24, 48, 4, 4, 1>
            <<<dim3(8, 4, 16), 144>>>(o2, c1c, gg1, g1wc, g1bc, c1n);
        deconv_v5<16, 8, 96, 12, 48, 8, 4, 1>
            <<<dim3(16, 2, 16), 144>>>(c1n, s1w, s1b, o1);

        // --- head -> output slice [t] ---
        head_k<<<dim3((16 * 192 * 192 + 255) / 256), 256>>>(
            o1, hw, hb, out + (size_t)t * 16 * 192 * 192);
    }
}

// round 6
// speedup vs baseline: 1.7847x; 1.7847x over previous
#include <cuda_runtime.h>

// ---------------------------------------------------------------------------
// Forecaster_PONI round 6: R2's proven register-blocked fp32 convs, fully
// fused (SPLIT=1, no epilogue kernels), grids retuned for occupancy.
// ---------------------------------------------------------------------------

__device__ __forceinline__ float lrelu_f(float v) { return v > 0.f ? v : 0.2f * v; }
__device__ __forceinline__ float sigm_f(float v)  { return 1.f / (1.f + __expf(-v)); }

// ------------------------------ scratch buffers ----------------------------
__device__ float g_e1[160 * 16 * 96 * 96];
__device__ float g_e2[160 * 64 * 48 * 48];
__device__ float g_e3[160 * 96 * 24 * 24];
__device__ float g_c3[2][16 * 96 * 24 * 24];
__device__ float g_c2[2][16 * 64 * 48 * 48];
__device__ float g_c1[2][16 * 16 * 96 * 96];
__device__ float g_g3[16 * 192 * 24 * 24];
__device__ float g_g2[16 * 128 * 48 * 48];
__device__ float g_g1[16 * 32 * 96 * 96];
__device__ float g_o3[16 * 64 * 48 * 48];
__device__ float g_o2[16 * 16 * 96 * 96];
__device__ float g_o1[16 * 8 * 192 * 192];

static const int NB = 16;  // batch

// ---------------------------------------------------------------------------
// conv3x3 (R2 design): stride-1 SAME conv over [x1 (C1) ++ x2 (C2)].
// Thread computes PXR rows x 4 cols of output, COT output channels.
// MODE 1 = gate conv. MODE 2 = candidate (x2 scaled by r on load; epilogue
// GRU combine). ACT: 1 lrelu, 2 sigmoid. SPLIT=1 used everywhere here.
// ---------------------------------------------------------------------------
template<int C1, int C2, int CO, int H, int W, int ACT, int MODE,
         int TY, int TX, int PXR, int CICH, int COT, int SPLIT>
__global__ void __launch_bounds__((TY / PXR) * (TX / 4))
conv3x3_v2(const float* __restrict__ x1, const float* __restrict__ x2,
           const float* __restrict__ gates, const float* __restrict__ wgt,
           const float* __restrict__ bias, float* __restrict__ out)
{
    constexpr int CI  = C1 + C2;
    constexpr int CIP = CI / SPLIT;
    constexpr int SH  = TY + 2, SW = TX + 2, SWP = (SW + 3) & ~3;
    constexpr int NT  = (TY / PXR) * (TX / 4);
    constexpr int TILES_X = W / TX;

    __shared__ __align__(16) float s_in[CICH][SH][SWP];
    __shared__ __align__(16) float s_w[CICH][COT][12];

    const int zs  = blockIdx.z;
    const int n   = zs / SPLIT;
    const int sp  = zs % SPLIT;
    const int cob = blockIdx.y * COT;
    const int ty0 = (blockIdx.x / TILES_X) * TY;
    const int tx0 = (blockIdx.x % TILES_X) * TX;
    const int tid = threadIdx.x;
    const int lx  = tid % (TX / 4);
    const int ly  = tid / (TX / 4);

    float acc[COT][PXR][4];
#pragma unroll
    for (int c = 0; c < COT; c++)
#pragma unroll
        for (int r = 0; r < PXR; r++)
#pragma unroll
            for (int j = 0; j < 4; j++) acc[c][r][j] = 0.f;

    const int ci_base = sp * CIP;
    for (int ci0 = 0; ci0 < CIP; ci0 += CICH) {
        for (int idx = tid; idx < CICH * SH * SW; idx += NT) {
            int c   = idx / (SH * SW);
            int rem = idx - c * (SH * SW);
            int iy  = rem / SW;
            int ix  = rem - iy * SW;
            int gy = ty0 + iy - 1, gx = tx0 + ix - 1;
            int ci = ci_base + ci0 + c;
            float v = 0.f;
            if ((unsigned)gy < (unsigned)H && (unsigned)gx < (unsigned)W) {
                if (ci < C1) {
                    v = x1[(((size_t)n * C1 + ci) * H + gy) * W + gx];
                } else {
                    int c2 = ci - C1;
                    v = x2[(((size_t)n * C2 + c2) * H + gy) * W + gx];
                    if (MODE == 2)
                        v *= gates[(((size_t)n * 2 * C2 + C2 + c2) * H + gy) * W + gx];
                }
            }
            s_in[c][iy][ix] = v;
        }
        for (int idx = tid; idx < CICH * COT * 9; idx += NT) {
            int c   = idx / (COT * 9);
            int rem = idx - c * (COT * 9);
            int co  = rem / 9;
            int k   = rem - co * 9;
            s_w[c][co][k] = wgt[((cob + co) * CI + (ci_base + ci0 + c)) * 9 + k];
        }
        __syncthreads();

#pragma unroll
        for (int c = 0; c < CICH; c++) {
            float p[PXR + 2][6];
#pragma unroll
            for (int r = 0; r < PXR + 2; r++) {
                float4 q  = *(const float4*)&s_in[c][PXR * ly + r][4 * lx];
                float2 q2 = *(const float2*)&s_in[c][PXR * ly + r][4 * lx + 4];
                p[r][0] = q.x; p[r][1] = q.y; p[r][2] = q.z; p[r][3] = q.w;
                p[r][4] = q2.x; p[r][5] = q2.y;
            }
#pragma unroll
            for (int co = 0; co < COT; co++) {
                float4 w0 = *(const float4*)&s_w[c][co][0];
                float4 w1 = *(const float4*)&s_w[c][co][4];
                float  w8 = s_w[c][co][8];
                float wk[9] = {w0.x, w0.y, w0.z, w0.w, w1.x, w1.y, w1.z, w1.w, w8};
#pragma unroll
                for (int ky = 0; ky < 3; ky++)
#pragma unroll
                    for (int kx = 0; kx < 3; kx++)
#pragma unroll
                        for (int r = 0; r < PXR; r++)
#pragma unroll
                            for (int cc = 0; cc < 4; cc++)
                                acc[co][r][cc] = fmaf(p[r + ky][cc + kx],
                                                      wk[ky * 3 + kx],
                                                      acc[co][r][cc]);
            }
        }
        __syncthreads();
    }

    const int oy = ty0 + PXR * ly, ox = tx0 + 4 * lx;
#pragma unroll
    for (int co = 0; co < COT; co++) {
        float bv = bias[cob + co];
#pragma unroll
        for (int r = 0; r < PXR; r++) {
            int y = oy + r;
            float v[4];
#pragma unroll
            for (int cc = 0; cc < 4; cc++) {
                float t = acc[co][r][cc] + bv;
                if (ACT == 1) t = lrelu_f(t);
                if (ACT == 2) t = sigm_f(t);
                v[cc] = t;
            }
            size_t off = (((size_t)n * CO + cob + co) * H + y) * W + ox;
            if (MODE == 2) {
                float4 z4 = *(const float4*)&gates[(((size_t)n * 2 * CO + cob + co) * H + y) * W + ox];
                float4 h4 = *(const float4*)&x2[off];
                v[0] = (1.f - z4.x) * h4.x + z4.x * v[0];
                v[1] = (1.f - z4.y) * h4.y + z4.y * v[1];
                v[2] = (1.f - z4.z) * h4.z + z4.z * v[2];
                v[3] = (1.f - z4.w) * h4.w + z4.w * v[3];
            }
            float4 o = {v[0], v[1], v[2], v[3]};
            *(float4*)&out[off] = o;
        }
    }
}

// ---------------------------------------------------------------------------
// deconv (R2 design): 4x4 stride-2 SAME transposed conv (unflipped kernel).
// Thread owns 2x2 input pixels -> 4x4 outputs, COT channels. FUSE=1: lrelu.
// ---------------------------------------------------------------------------
template<int CI, int CO, int HIN, int TY, int TX, int CICH, int COT, int SPLIT, int FUSE>
__global__ void __launch_bounds__((TY / 2) * (TX / 2))
deconv_v2(const float* __restrict__ x, const float* __restrict__ wgt,
          const float* __restrict__ bias, float* __restrict__ out)
{
    constexpr int WIN = HIN, HO = 2 * HIN, WO = 2 * HIN;
    constexpr int CIP = CI / SPLIT;
    constexpr int SH  = TY + 2, SW = TX + 2, SWP = (SW + 3) & ~3;
    constexpr int NT  = (TY / 2) * (TX / 2);
    constexpr int TILES_X = WIN / TX;

    __shared__ __align__(16) float s_in[CICH][SH][SWP];
    __shared__ __align__(16) float s_w[CICH][COT][16];

    const int zs  = blockIdx.z;
    const int n   = zs / SPLIT;
    const int sp  = zs % SPLIT;
    const int cob = blockIdx.y * COT;
    const int ty0 = (blockIdx.x / TILES_X) * TY;
    const int tx0 = (blockIdx.x % TILES_X) * TX;
    const int tid = threadIdx.x;
    const int lx  = tid % (TX / 2);
    const int ly  = tid / (TX / 2);

    float acc[COT][4][4];
#pragma unroll
    for (int c = 0; c < COT; c++)
#pragma unroll
        for (int u = 0; u < 4; u++)
#pragma unroll
            for (int v = 0; v < 4; v++) acc[c][u][v] = 0.f;

    const int ci_base = sp * CIP;
    for (int ci0 = 0; ci0 < CIP; ci0 += CICH) {
        for (int idx = tid; idx < CICH * SH * SW; idx += NT) {
            int c   = idx / (SH * SW);
            int rem = idx - c * (SH * SW);
            int iy  = rem / SW;
            int ix  = rem - iy * SW;
            int gy = ty0 + iy - 1, gx = tx0 + ix - 1;
            float v = 0.f;
            if ((unsigned)gy < (unsigned)HIN && (unsigned)gx < (unsigned)WIN)
                v = x[(((size_t)n * CI + (ci_base + ci0 + c)) * HIN + gy) * WIN + gx];
            s_in[c][iy][ix] = v;
        }
        for (int idx = tid; idx < CICH * COT * 16; idx += NT) {
            int c   = idx / (COT * 16);
            int rem = idx - c * (COT * 16);
            int co  = rem / 16;
            int k   = rem - co * 16;
            s_w[c][co][k] = wgt[((cob + co) * CI + (ci_base + ci0 + c)) * 16 + k];
        }
        __syncthreads();

#pragma unroll
        for (int c = 0; c < CICH; c++) {
            float p[4][4];
#pragma unroll
            for (int r = 0; r < 4; r++) {
                float2 a = *(const float2*)&s_in[c][2 * ly + r][2 * lx];
                float2 b = *(const float2*)&s_in[c][2 * ly + r][2 * lx + 2];
                p[r][0] = a.x; p[r][1] = a.y; p[r][2] = b.x; p[r][3] = b.y;
            }
#pragma unroll
            for (int co = 0; co < COT; co++) {
                float wk[16];
#pragma unroll
                for (int q = 0; q < 4; q++) {
                    float4 wv = *(const float4*)&s_w[c][co][4 * q];
                    wk[4 * q] = wv.x; wk[4 * q + 1] = wv.y;
                    wk[4 * q + 2] = wv.z; wk[4 * q + 3] = wv.w;
                }
#pragma unroll
                for (int u = 0; u < 4; u++)
#pragma unroll
                    for (int v = 0; v < 4; v++)
#pragma unroll
                        for (int a = 0; a < 2; a++)
#pragma unroll
                            for (int b = 0; b < 2; b++)
                                acc[co][u][v] = fmaf(
                                    p[(u >> 1) + (u & 1) + a][(v >> 1) + (v & 1) + b],
                                    wk[((u & 1) + 2 * a) * 4 + (v & 1) + 2 * b],
                                    acc[co][u][v]);
            }
        }
        __syncthreads();
    }

    const int orow0 = 2 * ty0 + 4 * ly;
    const int ocol0 = 2 * tx0 + 4 * lx;
#pragma unroll
    for (int co = 0; co < COT; co++) {
        float bv = bias[cob + co];
#pragma unroll
        for (int u = 0; u < 4; u++) {
            float4 v;
            v.x = lrelu_f(acc[co][u][0] + bv);
            v.y = lrelu_f(acc[co][u][1] + bv);
            v.z = lrelu_f(acc[co][u][2] + bv);
            v.w = lrelu_f(acc[co][u][3] + bv);
            *(float4*)&out[(((size_t)n * CO + cob + co) * HO + orow0 + u) * WO + ocol0] = v;
        }
    }
}

// ---------------------------------------------------------------------------
// Encoder: 3x3 stride-2 SAME conv. pad_lo = 0: out[y] uses in[2y + ky].
// REMAP folds [B,T]->[T,B] transpose into enc1's read.
// ---------------------------------------------------------------------------
template<int CI, int CO, int HIN, bool REMAP, int TY, int TX, int CICH, int COT>
__global__ void __launch_bounds__(TY * TX)
conv3x3s2_k(const float* __restrict__ x, const float* __restrict__ wgt,
            const float* __restrict__ bias, float* __restrict__ out)
{
    constexpr int WIN = HIN, HO = HIN / 2, WO = HIN / 2;
    constexpr int SH = 2 * TY + 1, SW = 2 * TX + 1;
    constexpr int NT = TY * TX;
    constexpr int TILES_X = (WO + TX - 1) / TX;
    __shared__ float s_in[CICH][SH][SW];
    __shared__ float s_w[CICH][COT][9];

    const int n   = blockIdx.z;
    const int cob = blockIdx.y * COT;
    const int ty0 = (blockIdx.x / TILES_X) * TY;
    const int tx0 = (blockIdx.x % TILES_X) * TX;
    const int tid = threadIdx.x;
    const int lx  = tid % TX;
    const int ly  = tid / TX;

    float acc[COT];
#pragma unroll
    for (int c = 0; c < COT; c++) acc[c] = 0.f;

    for (int ci0 = 0; ci0 < CI; ci0 += CICH) {
        for (int idx = tid; idx < CICH * SH * SW; idx += NT) {
            int c   = idx / (SH * SW);
            int rem = idx - c * (SH * SW);
            int iy  = rem / SW;
            int ix  = rem - iy * SW;
            int gy = 2 * ty0 + iy, gx = 2 * tx0 + ix;
            int ci = ci0 + c;
            float v = 0.f;
            if (gy < HIN && gx < WIN) {
                int frame = REMAP ? ((n % 16) * 10 + n / 16) : n;
                v = x[(((size_t)frame * CI + ci) * HIN + gy) * WIN + gx];
            }
            s_in[c][iy][ix] = v;
        }
        for (int idx = tid; idx < CICH * COT * 9; idx += NT) {
            int c   = idx / (COT * 9);
            int rem = idx - c * (COT * 9);
            int co  = rem / 9;
            int k   = rem - co * 9;
            s_w[c][co][k] = wgt[((cob + co) * CI + (ci0 + c)) * 9 + k];
        }
        __syncthreads();

        for (int c = 0; c < CICH; c++) {
            float p[3][3];
#pragma unroll
            for (int r = 0; r < 3; r++)
#pragma unroll
                for (int cc = 0; cc < 3; cc++)
                    p[r][cc] = s_in[c][2 * ly + r][2 * lx + cc];
#pragma unroll
            for (int co = 0; co < COT; co++) {
#pragma unroll
                for (int k = 0; k < 9; k++)
                    acc[co] = fmaf(p[k / 3][k % 3], s_w[c][co][k], acc[co]);
            }
        }
        __syncthreads();
    }

    const int oy = ty0 + ly, ox = tx0 + lx;
    if (oy < HO && ox < WO) {
#pragma unroll
        for (int co = 0; co < COT; co++) {
            float v = lrelu_f(acc[co] + bias[cob + co]);
            out[(((size_t)n * CO + cob + co) * HO + oy) * WO + ox] = v;
        }
    }
}

// ---------------------------------------------------------------------------
// Head: 3x3 conv, 8 -> 1 channels, 192x192.
// ---------------------------------------------------------------------------
__global__ void head_k(const float* __restrict__ x, const float* __restrict__ w,
                       const float* __restrict__ b, float* __restrict__ out)
{
    __shared__ float sw[72];
    __shared__ float sb;
    if (threadIdx.x < 72) sw[threadIdx.x] = w[threadIdx.x];
    if (threadIdx.x == 0) sb = b[0];
    __syncthreads();

    const int HW = 192 * 192;
    int idx = blockIdx.x * blockDim.x + threadIdx.x;
    if (idx >= 16 * HW) return;
    int n   = idx / HW;
    int rem = idx - n * HW;
    int y   = rem / 192;
    int xq  = rem - y * 192;

    float acc = sb;
#pragma unroll
    for (int ci = 0; ci < 8; ci++) {
        const float* xp = x + (size_t)(n * 8 + ci) * HW;
#pragma unroll
        for (int ky = 0; ky < 3; ky++) {
            int yy = y + ky - 1;
            if ((unsigned)yy >= 192u) continue;
#pragma unroll
            for (int kx = 0; kx < 3; kx++) {
                int xx = xq + kx - 1;
                if ((unsigned)xx >= 192u) continue;
                acc = fmaf(xp[yy * 192 + xx], sw[ci * 9 + ky * 3 + kx], acc);
            }
        }
    }
    out[idx] = acc;
}

// ---------------------------------------------------------------------------
// host
// ---------------------------------------------------------------------------
extern "C" void kernel_launch(void* const* d_in, const int* in_sizes, int n_in,
                              void* d_out, int out_size)
{
    const float* h1     = (const float*)d_in[0];
    const float* h2     = (const float*)d_in[1];
    const float* h3     = (const float*)d_in[2];
    const float* y_add  = (const float*)d_in[3];
    const float* enc_w1 = (const float*)d_in[4];
    const float* enc_b1 = (const float*)d_in[5];
    const float* enc_w2 = (const float*)d_in[6];
    const float* enc_b2 = (const float*)d_in[7];
    const float* enc_w3 = (const float*)d_in[8];
    const float* enc_b3 = (const float*)d_in[9];
    const float* g3wg   = (const float*)d_in[10];
    const float* g3bg   = (const float*)d_in[11];
    const float* g3wc   = (const float*)d_in[12];
    const float* g3bc   = (const float*)d_in[13];
    const float* g2wg   = (const float*)d_in[14];
    const float* g2bg   = (const float*)d_in[15];
    const float* g2wc   = (const float*)d_in[16];
    const float* g2bc   = (const float*)d_in[17];
    const float* g1wg   = (const float*)d_in[18];
    const float* g1bg   = (const float*)d_in[19];
    const float* g1wc   = (const float*)d_in[20];
    const float* g1bc   = (const float*)d_in[21];
    const float* s3w    = (const float*)d_in[22];
    const float* s3b    = (const float*)d_in[23];
    const float* s2w    = (const float*)d_in[24];
    const float* s2b    = (const float*)d_in[25];
    const float* s1w    = (const float*)d_in[26];
    const float* s1b    = (const float*)d_in[27];
    const float* hw     = (const float*)d_in[28];
    const float* hb     = (const float*)d_in[29];
    float* out = (float*)d_out;

    float *e1, *e2, *e3, *c3b, *c2b, *c1b, *gg3, *gg2, *gg1, *o3, *o2, *o1;
    cudaGetSymbolAddress((void**)&e1, g_e1);
    cudaGetSymbolAddress((void**)&e2, g_e2);
    cudaGetSymbolAddress((void**)&e3, g_e3);
    cudaGetSymbolAddress((void**)&c3b, g_c3);
    cudaGetSymbolAddress((void**)&c2b, g_c2);
    cudaGetSymbolAddress((void**)&c1b, g_c1);
    cudaGetSymbolAddress((void**)&gg3, g_g3);
    cudaGetSymbolAddress((void**)&gg2, g_g2);
    cudaGetSymbolAddress((void**)&gg1, g_g1);
    cudaGetSymbolAddress((void**)&o3, g_o3);
    cudaGetSymbolAddress((void**)&o2, g_o2);
    cudaGetSymbolAddress((void**)&o1, g_o1);

    const size_t SZ3 = (size_t)16 * 96 * 24 * 24;
    const size_t SZ2 = (size_t)16 * 64 * 48 * 48;
    const size_t SZ1 = (size_t)16 * 16 * 96 * 96;

    // -------- encoder over all 160 frames (transpose folded into enc1) -----
    conv3x3s2_k<1, 16, 192, true, 16, 16, 1, 16><<<dim3(36, 1, 160), 256>>>(
        y_add, enc_w1, enc_b1, e1);
    conv3x3s2_k<16, 64, 96, false, 16, 16, 8, 8><<<dim3(9, 8, 160), 256>>>(
        e1, enc_w2, enc_b2, e2);
    conv3x3s2_k<64, 96, 48, false, 16, 16, 8, 8><<<dim3(4, 12, 160), 256>>>(
        e2, enc_w3, enc_b3, e3);

    cudaMemcpyAsync(c3b, h3, SZ3 * sizeof(float), cudaMemcpyDeviceToDevice);
    cudaMemcpyAsync(c2b, h2, SZ2 * sizeof(float), cudaMemcpyDeviceToDevice);
    cudaMemcpyAsync(c1b, h1, SZ1 * sizeof(float), cudaMemcpyDeviceToDevice);

    for (int t = 0; t < 10; t++) {
        const float* x3 = e3 + (size_t)t * 16 * 96 * 24 * 24;
        float* c3c = c3b + (size_t)(t & 1) * SZ3;
        float* c3n = c3b + (size_t)((t + 1) & 1) * SZ3;
        float* c2c = c2b + (size_t)(t & 1) * SZ2;
        float* c2n = c2b + (size_t)((t + 1) & 1) * SZ2;
        float* c1c = c1b + (size_t)(t & 1) * SZ1;
        float* c1n = c1b + (size_t)((t + 1) & 1) * SZ1;

        // --- level 3 (24x24, 96 ch) ---
        conv3x3_v2<96, 96, 192, 24, 24, 2, 1, 24, 24, 1, 8, 4, 1>
            <<<dim3(1, 48, 16), 144>>>(x3, c3c, nullptr, g3wg, g3bg, gg3);
        conv3x3_v2<96, 96, 96, 24, 24, 1, 2, 24, 24, 1, 8, 4, 1>
            <<<dim3(1, 24, 16), 144>>>(x3, c3c, gg3, g3wc, g3bc, c3n);
        deconv_v2<96, 64, 24, 24, 24, 8, 4, 1, 1>
            <<<dim3(1, 16, 16), 144>>>(c3n, s3w, s3b, o3);

        // --- level 2 (48x48, 64 ch) ---
        conv3x3_v2<64, 64, 128, 48, 48, 2, 1, 24, 48, 2, 4, 8, 1>
            <<<dim3(2, 16, 16), 144>>>(o3, c2c, nullptr, g2wg, g2bg, gg2);
        conv3x3_v2<64, 64, 64, 48, 48, 1, 2, 24, 48, 2, 4, 8, 1>
            <<<dim3(2, 8, 16), 144>>>(o3, c2c, gg2, g2wc, g2bc, c2n);
        deconv_v2<64, 16, 48, 16, 48, 4, 2, 1, 1>
            <<<dim3(3, 8, 16), 192>>>(c2n, s2w, s2b, o2);

        // --- level 1 (96x96, 16 ch) ---
        conv3x3_v2<16, 16, 32, 96, 96, 2, 1, 24, 48, 2, 4, 8, 1>
            <<<dim3(8, 4, 16), 144>>>(o2, c1c, nullptr, g1wg, g1bg, gg1);
        conv3x3_v2<16, 16, 16, 96, 96, 1, 2, 24, 48, 2, 4, 4, 1>
            <<<dim3(8, 4, 16), 144>>>(o2, c1c, gg1, g1wc, g1bc, c1n);
        deconv_v2<16, 8, 96, 16, 48, 4, 4, 1, 1>
            <<<dim3(12, 2, 16), 192>>>(c1n, s1w, s1b, o1);

        // --- head -> output slice [t] ---
        head_k<<<dim3((16 * 192 * 192 + 255) / 256), 256>>>(
            o1, hw, hb, out + (size_t)t * 16 * 192 * 192);
    }
}

// round 7
// speedup vs baseline: 2.6072x; 1.4608x over previous
#include <cuda_runtime.h>

// ---------------------------------------------------------------------------
// Forecaster_PONI round 7: R1 baseline schedule, with ONLY the L3 level
// (24x24) replaced by R2's measured-faster split-K kernels + epilogues.
// ---------------------------------------------------------------------------

__device__ __forceinline__ float lrelu_f(float v) { return v > 0.f ? v : 0.2f * v; }
__device__ __forceinline__ float sigm_f(float v)  { return 1.f / (1.f + __expf(-v)); }

// ------------------------------ scratch buffers ----------------------------
__device__ float g_e1[160 * 16 * 96 * 96];
__device__ float g_e2[160 * 64 * 48 * 48];
__device__ float g_e3[160 * 96 * 24 * 24];
__device__ float g_c3[2][16 * 96 * 24 * 24];
__device__ float g_c2[2][16 * 64 * 48 * 48];
__device__ float g_c1[2][16 * 16 * 96 * 96];
__device__ float g_g3[16 * 192 * 24 * 24];
__device__ float g_g2[16 * 128 * 48 * 48];
__device__ float g_g1[16 * 32 * 96 * 96];
__device__ float g_o3[16 * 64 * 48 * 48];
__device__ float g_o2[16 * 16 * 96 * 96];
__device__ float g_o1[16 * 8 * 192 * 192];
__device__ float g_part[4 * 16 * 192 * 24 * 24 + 2 * 16 * 64 * 48 * 48];

static const int NB = 16;  // batch

// ---------------------------------------------------------------------------
// R2 conv3x3: stride-1 SAME conv over [x1 (C1) ++ x2 (C2)].
// Thread computes PXR rows x 4 cols, COT output channels.
// SPLIT>1: raw partials to out[sp]. MODE 2: x2 scaled by r on load.
// ---------------------------------------------------------------------------
template<int C1, int C2, int CO, int H, int W, int ACT, int MODE,
         int TY, int TX, int PXR, int CICH, int COT, int SPLIT>
__global__ void __launch_bounds__((TY / PXR) * (TX / 4))
conv3x3_v2(const float* __restrict__ x1, const float* __restrict__ x2,
           const float* __restrict__ gates, const float* __restrict__ wgt,
           const float* __restrict__ bias, float* __restrict__ out)
{
    constexpr int CI  = C1 + C2;
    constexpr int CIP = CI / SPLIT;
    constexpr int SH  = TY + 2, SW = TX + 2, SWP = (SW + 3) & ~3;
    constexpr int NT  = (TY / PXR) * (TX / 4);
    constexpr int TILES_X = W / TX;

    __shared__ __align__(16) float s_in[CICH][SH][SWP];
    __shared__ __align__(16) float s_w[CICH][COT][12];

    const int zs  = blockIdx.z;
    const int n   = zs / SPLIT;
    const int sp  = zs % SPLIT;
    const int cob = blockIdx.y * COT;
    const int ty0 = (blockIdx.x / TILES_X) * TY;
    const int tx0 = (blockIdx.x % TILES_X) * TX;
    const int tid = threadIdx.x;
    const int lx  = tid % (TX / 4);
    const int ly  = tid / (TX / 4);

    float acc[COT][PXR][4];
#pragma unroll
    for (int c = 0; c < COT; c++)
#pragma unroll
        for (int r = 0; r < PXR; r++)
#pragma unroll
            for (int j = 0; j < 4; j++) acc[c][r][j] = 0.f;

    const int ci_base = sp * CIP;
    for (int ci0 = 0; ci0 < CIP; ci0 += CICH) {
        for (int idx = tid; idx < CICH * SH * SW; idx += NT) {
            int c   = idx / (SH * SW);
            int rem = idx - c * (SH * SW);
            int iy  = rem / SW;
            int ix  = rem - iy * SW;
            int gy = ty0 + iy - 1, gx = tx0 + ix - 1;
            int ci = ci_base + ci0 + c;
            float v = 0.f;
            if ((unsigned)gy < (unsigned)H && (unsigned)gx < (unsigned)W) {
                if (ci < C1) {
                    v = x1[(((size_t)n * C1 + ci) * H + gy) * W + gx];
                } else {
                    int c2 = ci - C1;
                    v = x2[(((size_t)n * C2 + c2) * H + gy) * W + gx];
                    if (MODE == 2)
                        v *= gates[(((size_t)n * 2 * C2 + C2 + c2) * H + gy) * W + gx];
                }
            }
            s_in[c][iy][ix] = v;
        }
        for (int idx = tid; idx < CICH * COT * 9; idx += NT) {
            int c   = idx / (COT * 9);
            int rem = idx - c * (COT * 9);
            int co  = rem / 9;
            int k   = rem - co * 9;
            s_w[c][co][k] = wgt[((cob + co) * CI + (ci_base + ci0 + c)) * 9 + k];
        }
        __syncthreads();

#pragma unroll
        for (int c = 0; c < CICH; c++) {
            float p[PXR + 2][6];
#pragma unroll
            for (int r = 0; r < PXR + 2; r++) {
                float4 q  = *(const float4*)&s_in[c][PXR * ly + r][4 * lx];
                float2 q2 = *(const float2*)&s_in[c][PXR * ly + r][4 * lx + 4];
                p[r][0] = q.x; p[r][1] = q.y; p[r][2] = q.z; p[r][3] = q.w;
                p[r][4] = q2.x; p[r][5] = q2.y;
            }
#pragma unroll
            for (int co = 0; co < COT; co++) {
                float4 w0 = *(const float4*)&s_w[c][co][0];
                float4 w1 = *(const float4*)&s_w[c][co][4];
                float  w8 = s_w[c][co][8];
                float wk[9] = {w0.x, w0.y, w0.z, w0.w, w1.x, w1.y, w1.z, w1.w, w8};
#pragma unroll
                for (int ky = 0; ky < 3; ky++)
#pragma unroll
                    for (int kx = 0; kx < 3; kx++)
#pragma unroll
                        for (int r = 0; r < PXR; r++)
#pragma unroll
                            for (int cc = 0; cc < 4; cc++)
                                acc[co][r][cc] = fmaf(p[r + ky][cc + kx],
                                                      wk[ky * 3 + kx],
                                                      acc[co][r][cc]);
            }
        }
        __syncthreads();
    }

    const int oy = ty0 + PXR * ly, ox = tx0 + 4 * lx;
    if (SPLIT > 1) {
#pragma unroll
        for (int co = 0; co < COT; co++)
#pragma unroll
            for (int r = 0; r < PXR; r++) {
                float4 v = {acc[co][r][0], acc[co][r][1], acc[co][r][2], acc[co][r][3]};
                *(float4*)&out[(((size_t)(sp * NB + n) * CO + cob + co) * H + oy + r) * W + ox] = v;
            }
    } else {
#pragma unroll
        for (int co = 0; co < COT; co++) {
            float bv = bias[cob + co];
#pragma unroll
            for (int r = 0; r < PXR; r++) {
                int y = oy + r;
                float v[4];
#pragma unroll
                for (int cc = 0; cc < 4; cc++) {
                    float t = acc[co][r][cc] + bv;
                    if (ACT == 1) t = lrelu_f(t);
                    if (ACT == 2) t = sigm_f(t);
                    v[cc] = t;
                }
                size_t off = (((size_t)n * CO + cob + co) * H + y) * W + ox;
                if (MODE == 2) {
                    float4 z4 = *(const float4*)&gates[(((size_t)n * 2 * CO + cob + co) * H + y) * W + ox];
                    float4 h4 = *(const float4*)&x2[off];
                    v[0] = (1.f - z4.x) * h4.x + z4.x * v[0];
                    v[1] = (1.f - z4.y) * h4.y + z4.y * v[1];
                    v[2] = (1.f - z4.z) * h4.z + z4.z * v[2];
                    v[3] = (1.f - z4.w) * h4.w + z4.w * v[3];
                }
                float4 o = {v[0], v[1], v[2], v[3]};
                *(float4*)&out[off] = o;
            }
        }
    }
}

// ---------------------------------------------------------------------------
// R2 deconv: 4x4 stride-2 SAME transposed conv (unflipped kernel).
// Thread owns 2x2 input pixels -> 4x4 outputs. FUSE=0: raw partial write.
// ---------------------------------------------------------------------------
template<int CI, int CO, int HIN, int TY, int TX, int CICH, int COT, int SPLIT, int FUSE>
__global__ void __launch_bounds__((TY / 2) * (TX / 2))
deconv_v2(const float* __restrict__ x, const float* __restrict__ wgt,
          const float* __restrict__ bias, float* __restrict__ out)
{
    constexpr int WIN = HIN, HO = 2 * HIN, WO = 2 * HIN;
    constexpr int CIP = CI / SPLIT;
    constexpr int SH  = TY + 2, SW = TX + 2, SWP = (SW + 3) & ~3;
    constexpr int NT  = (TY / 2) * (TX / 2);
    constexpr int TILES_X = WIN / TX;

    __shared__ __align__(16) float s_in[CICH][SH][SWP];
    __shared__ __align__(16) float s_w[CICH][COT][16];

    const int zs  = blockIdx.z;
    const int n   = zs / SPLIT;
    const int sp  = zs % SPLIT;
    const int cob = blockIdx.y * COT;
    const int ty0 = (blockIdx.x / TILES_X) * TY;
    const int tx0 = (blockIdx.x % TILES_X) * TX;
    const int tid = threadIdx.x;
    const int lx  = tid % (TX / 2);
    const int ly  = tid / (TX / 2);

    float acc[COT][4][4];
#pragma unroll
    for (int c = 0; c < COT; c++)
#pragma unroll
        for (int u = 0; u < 4; u++)
#pragma unroll
            for (int v = 0; v < 4; v++) acc[c][u][v] = 0.f;

    const int ci_base = sp * CIP;
    for (int ci0 = 0; ci0 < CIP; ci0 += CICH) {
        for (int idx = tid; idx < CICH * SH * SW; idx += NT) {
            int c   = idx / (SH * SW);
            int rem = idx - c * (SH * SW);
            int iy  = rem / SW;
            int ix  = rem - iy * SW;
            int gy = ty0 + iy - 1, gx = tx0 + ix - 1;
            float v = 0.f;
            if ((unsigned)gy < (unsigned)HIN && (unsigned)gx < (unsigned)WIN)
                v = x[(((size_t)n * CI + (ci_base + ci0 + c)) * HIN + gy) * WIN + gx];
            s_in[c][iy][ix] = v;
        }
        for (int idx = tid; idx < CICH * COT * 16; idx += NT) {
            int c   = idx / (COT * 16);
            int rem = idx - c * (COT * 16);
            int co  = rem / 16;
            int k   = rem - co * 16;
            s_w[c][co][k] = wgt[((cob + co) * CI + (ci_base + ci0 + c)) * 16 + k];
        }
        __syncthreads();

#pragma unroll
        for (int c = 0; c < CICH; c++) {
            float p[4][4];
#pragma unroll
            for (int r = 0; r < 4; r++) {
                float2 a = *(const float2*)&s_in[c][2 * ly + r][2 * lx];
                float2 b = *(const float2*)&s_in[c][2 * ly + r][2 * lx + 2];
                p[r][0] = a.x; p[r][1] = a.y; p[r][2] = b.x; p[r][3] = b.y;
            }
#pragma unroll
            for (int co = 0; co < COT; co++) {
                float wk[16];
#pragma unroll
                for (int q = 0; q < 4; q++) {
                    float4 wv = *(const float4*)&s_w[c][co][4 * q];
                    wk[4 * q] = wv.x; wk[4 * q + 1] = wv.y;
                    wk[4 * q + 2] = wv.z; wk[4 * q + 3] = wv.w;
                }
#pragma unroll
                for (int u = 0; u < 4; u++)
#pragma unroll
                    for (int v = 0; v < 4; v++)
#pragma unroll
                        for (int a = 0; a < 2; a++)
#pragma unroll
                            for (int b = 0; b < 2; b++)
                                acc[co][u][v] = fmaf(
                                    p[(u >> 1) + (u & 1) + a][(v >> 1) + (v & 1) + b],
                                    wk[((u & 1) + 2 * a) * 4 + (v & 1) + 2 * b],
                                    acc[co][u][v]);
            }
        }
        __syncthreads();
    }

    const int orow0 = 2 * ty0 + 4 * ly;
    const int ocol0 = 2 * tx0 + 4 * lx;
#pragma unroll
    for (int co = 0; co < COT; co++) {
        float bv = FUSE ? bias[cob + co] : 0.f;
#pragma unroll
        for (int u = 0; u < 4; u++) {
            float4 v;
            if (FUSE) {
                v.x = lrelu_f(acc[co][u][0] + bv);
                v.y = lrelu_f(acc[co][u][1] + bv);
                v.z = lrelu_f(acc[co][u][2] + bv);
                v.w = lrelu_f(acc[co][u][3] + bv);
                *(float4*)&out[(((size_t)n * CO + cob + co) * HO + orow0 + u) * WO + ocol0] = v;
            } else {
                v.x = acc[co][u][0]; v.y = acc[co][u][1];
                v.z = acc[co][u][2]; v.w = acc[co][u][3];
                *(float4*)&out[(((size_t)(sp * NB + n) * CO + cob + co) * HO + orow0 + u) * WO + ocol0] = v;
            }
        }
    }
}

// ---------------------------------------------------------------------------
// Epilogue: sum SPLIT partials + bias; MODE 0 lrelu, 1 sigmoid,
// 2 GRU combine out = (1-z)*h + z*lrelu(s).
// ---------------------------------------------------------------------------
template<int CO, int HW, int SPLIT, int MODE>
__global__ void epi_k(const float* __restrict__ part, const float* __restrict__ bias,
                      const float* __restrict__ gates, const float* __restrict__ hprev,
                      float* __restrict__ out)
{
    constexpr size_t TOT = (size_t)NB * CO * HW;
    size_t i = ((size_t)blockIdx.x * blockDim.x + threadIdx.x) * 4;
    if (i >= TOT) return;
    int c   = (int)((i / HW) % CO);
    float4 s = *(const float4*)&part[i];
#pragma unroll
    for (int sp = 1; sp < SPLIT; sp++) {
        float4 q = *(const float4*)&part[(size_t)sp * TOT + i];
        s.x += q.x; s.y += q.y; s.z += q.z; s.w += q.w;
    }
    float bv = bias[c];
    s.x += bv; s.y += bv; s.z += bv; s.w += bv;
    if (MODE == 0) {
        s.x = lrelu_f(s.x); s.y = lrelu_f(s.y); s.z = lrelu_f(s.z); s.w = lrelu_f(s.w);
    } else if (MODE == 1) {
        s.x = sigm_f(s.x); s.y = sigm_f(s.y); s.z = sigm_f(s.z); s.w = sigm_f(s.w);
    } else {
        int n   = (int)(i / ((size_t)HW * CO));
        size_t pix = i % HW;
        float4 z = *(const float4*)&gates[((size_t)(n * 2 * CO + c)) * HW + pix];
        float4 h = *(const float4*)&hprev[i];
        s.x = (1.f - z.x) * h.x + z.x * lrelu_f(s.x);
        s.y = (1.f - z.y) * h.y + z.y * lrelu_f(s.y);
        s.z = (1.f - z.z) * h.z + z.z * lrelu_f(s.z);
        s.w = (1.f - z.w) * h.w + z.w * lrelu_f(s.w);
    }
    *(float4*)&out[i] = s;
}

// ---------------------------------------------------------------------------
// R1 conv3x3: 2x2 px x COT per thread (used at L2/L1 — part of 24.8ms base).
// ---------------------------------------------------------------------------
template<int C1, int C2, int CO, int H, int W, int ACT, int MODE,
         int TY, int TX, int CICH, int COT>
__global__ void __launch_bounds__((TY / 2) * (TX / 2))
conv3x3_k(const float* __restrict__ x1, const float* __restrict__ x2,
          const float* __restrict__ gates, const float* __restrict__ wgt,
          const float* __restrict__ bias, float* __restrict__ out)
{
    constexpr int CI = C1 + C2;
    constexpr int SH = TY + 2, SW = TX + 2;
    constexpr int NT = (TY / 2) * (TX / 2);
    constexpr int TILES_X = (W + TX - 1) / TX;
    __shared__ float s_in[CICH][SH][SW];
    __shared__ float s_w[CICH][COT][9];

    const int n   = blockIdx.z;
    const int cob = blockIdx.y * COT;
    const int ty0 = (blockIdx.x / TILES_X) * TY;
    const int tx0 = (blockIdx.x % TILES_X) * TX;
    const int tid = threadIdx.x;
    const int lx  = tid % (TX / 2);
    const int ly  = tid / (TX / 2);

    float acc[COT][2][2];
#pragma unroll
    for (int c = 0; c < COT; c++) {
        acc[c][0][0] = acc[c][0][1] = acc[c][1][0] = acc[c][1][1] = 0.f;
    }

    for (int ci0 = 0; ci0 < CI; ci0 += CICH) {
        for (int idx = tid; idx < CICH * SH * SW; idx += NT) {
            int c   = idx / (SH * SW);
            int rem = idx - c * (SH * SW);
            int iy  = rem / SW;
            int ix  = rem - iy * SW;
            int gy = ty0 + iy - 1, gx = tx0 + ix - 1;
            int ci = ci0 + c;
            float v = 0.f;
            if ((unsigned)gy < (unsigned)H && (unsigned)gx < (unsigned)W) {
                if (ci < C1) {
                    v = x1[(((size_t)n * C1 + ci) * H + gy) * W + gx];
                } else {
                    int c2 = ci - C1;
                    v = x2[(((size_t)n * C2 + c2) * H + gy) * W + gx];
                    if (MODE == 2)
                        v *= gates[(((size_t)n * 2 * C2 + C2 + c2) * H + gy) * W + gx];
                }
            }
            s_in[c][iy][ix] = v;
        }
        for (int idx = tid; idx < CICH * COT * 9; idx += NT) {
            int c   = idx / (COT * 9);
            int rem = idx - c * (COT * 9);
            int co  = rem / 9;
            int k   = rem - co * 9;
            s_w[c][co][k] = wgt[((cob + co) * CI + (ci0 + c)) * 9 + k];
        }
        __syncthreads();

        for (int c = 0; c < CICH; c++) {
            float p[4][4];
#pragma unroll
            for (int i = 0; i < 4; i++)
#pragma unroll
                for (int j = 0; j < 4; j++)
                    p[i][j] = s_in[c][2 * ly + i][2 * lx + j];
#pragma unroll
            for (int co = 0; co < COT; co++) {
#pragma unroll
                for (int ky = 0; ky < 3; ky++)
#pragma unroll
                    for (int kx = 0; kx < 3; kx++) {
                        float wv = s_w[c][co][ky * 3 + kx];
                        acc[co][0][0] = fmaf(p[ky][kx],         wv, acc[co][0][0]);
                        acc[co][0][1] = fmaf(p[ky][kx + 1],     wv, acc[co][0][1]);
                        acc[co][1][0] = fmaf(p[ky + 1][kx],     wv, acc[co][1][0]);
                        acc[co][1][1] = fmaf(p[ky + 1][kx + 1], wv, acc[co][1][1]);
                    }
            }
        }
        __syncthreads();
    }

    const int oy = ty0 + 2 * ly, ox = tx0 + 2 * lx;
#pragma unroll
    for (int co = 0; co < COT; co++) {
        float bv = bias[cob + co];
#pragma unroll
        for (int i = 0; i < 2; i++)
#pragma unroll
            for (int j = 0; j < 2; j++) {
                int y = oy + i, x = ox + j;
                if (y < H && x < W) {
                    float v = acc[co][i][j] + bv;
                    if (ACT == 1) v = lrelu_f(v);
                    if (ACT == 2) v = sigm_f(v);
                    size_t off = (((size_t)n * CO + cob + co) * H + y) * W + x;
                    if (MODE == 2) {
                        float z = gates[(((size_t)n * 2 * CO + cob + co) * H + y) * W + x];
                        float h = x2[off];
                        v = (1.f - z) * h + z * v;
                    }
                    out[off] = v;
                }
            }
    }
}

// ---------------------------------------------------------------------------
// R1 deconv: 4x4 stride-2 SAME transposed conv, fused lrelu (L2/L1 levels).
// ---------------------------------------------------------------------------
template<int CI, int CO, int HIN, int TY, int TX, int CICH, int COT>
__global__ void __launch_bounds__(TY * TX)
deconv4x4_k(const float* __restrict__ x, const float* __restrict__ wgt,
            const float* __restrict__ bias, float* __restrict__ out)
{
    constexpr int WIN = HIN, HO = 2 * HIN, WO = 2 * HIN;
    constexpr int SH = TY + 2, SW = TX + 2;
    constexpr int NT = TY * TX;
    constexpr int TILES_X = (WIN + TX - 1) / TX;
    __shared__ float s_in[CICH][SH][SW];
    __shared__ float s_w[CICH][COT][16];

    const int n   = blockIdx.z;
    const int cob = blockIdx.y * COT;
    const int ty0 = (blockIdx.x / TILES_X) * TY;
    const int tx0 = (blockIdx.x % TILES_X) * TX;
    const int tid = threadIdx.x;
    const int lx  = tid % TX;
    const int ly  = tid / TX;

    float acc[COT][2][2];
#pragma unroll
    for (int c = 0; c < COT; c++) {
        acc[c][0][0] = acc[c][0][1] = acc[c][1][0] = acc[c][1][1] = 0.f;
    }

    for (int ci0 = 0; ci0 < CI; ci0 += CICH) {
        for (int idx = tid; idx < CICH * SH * SW; idx += NT) {
            int c   = idx / (SH * SW);
            int rem = idx - c * (SH * SW);
            int iy  = rem / SW;
            int ix  = rem - iy * SW;
            int gy = ty0 + iy - 1, gx = tx0 + ix - 1;
            float v = 0.f;
            if ((unsigned)gy < (unsigned)HIN && (unsigned)gx < (unsigned)WIN)
                v = x[(((size_t)n * CI + (ci0 + c)) * HIN + gy) * WIN + gx];
            s_in[c][iy][ix] = v;
        }
        for (int idx = tid; idx < CICH * COT * 16; idx += NT) {
            int c   = idx / (COT * 16);
            int rem = idx - c * (COT * 16);
            int co  = rem / 16;
            int k   = rem - co * 16;
            s_w[c][co][k] = wgt[((cob + co) * CI + (ci0 + c)) * 16 + k];
        }
        __syncthreads();

        for (int c = 0; c < CICH; c++) {
            float p[3][3];
#pragma unroll
            for (int r = 0; r < 3; r++)
#pragma unroll
                for (int cc = 0; cc < 3; cc++)
                    p[r][cc] = s_in[c][ly + r][lx + cc];
#pragma unroll
            for (int co = 0; co < COT; co++) {
#pragma unroll
                for (int dy = 0; dy < 2; dy++)
#pragma unroll
                    for (int dx = 0; dx < 2; dx++)
#pragma unroll
                        for (int a = 0; a < 2; a++)
#pragma unroll
                            for (int b = 0; b < 2; b++)
                                acc[co][dy][dx] =
                                    fmaf(p[a + dy][b + dx],
                                         s_w[c][co][(dy + 2 * a) * 4 + (dx + 2 * b)],
                                         acc[co][dy][dx]);
            }
        }
        __syncthreads();
    }

    const int iy = ty0 + ly, ix = tx0 + lx;
    if (iy < HIN && ix < WIN) {
#pragma unroll
        for (int co = 0; co < COT; co++) {
            float bv = bias[cob + co];
#pragma unroll
            for (int dy = 0; dy < 2; dy++)
#pragma unroll
                for (int dx = 0; dx < 2; dx++) {
                    float v = lrelu_f(acc[co][dy][dx] + bv);
                    out[(((size_t)n * CO + cob + co) * HO + 2 * iy + dy) * WO + 2 * ix + dx] = v;
                }
        }
    }
}

// ---------------------------------------------------------------------------
// Encoder: 3x3 stride-2 SAME conv. REMAP folds [B,T]->[T,B] into enc1's read.
// ---------------------------------------------------------------------------
template<int CI, int CO, int HIN, bool REMAP, int TY, int TX, int CICH, int COT>
__global__ void __launch_bounds__(TY * TX)
conv3x3s2_k(const float* __restrict__ x, const float* __restrict__ wgt,
            const float* __restrict__ bias, float* __restrict__ out)
{
    constexpr int WIN = HIN, HO = HIN / 2, WO = HIN / 2;
    constexpr int SH = 2 * TY + 1, SW = 2 * TX + 1;
    constexpr int NT = TY * TX;
    constexpr int TILES_X = (WO + TX - 1) / TX;
    __shared__ float s_in[CICH][SH][SW];
    __shared__ float s_w[CICH][COT][9];

    const int n   = blockIdx.z;
    const int cob = blockIdx.y * COT;
    const int ty0 = (blockIdx.x / TILES_X) * TY;
    const int tx0 = (blockIdx.x % TILES_X) * TX;
    const int tid = threadIdx.x;
    const int lx  = tid % TX;
    const int ly  = tid / TX;

    float acc[COT];
#pragma unroll
    for (int c = 0; c < COT; c++) acc[c] = 0.f;

    for (int ci0 = 0; ci0 < CI; ci0 += CICH) {
        for (int idx = tid; idx < CICH * SH * SW; idx += NT) {
            int c   = idx / (SH * SW);
            int rem = idx - c * (SH * SW);
            int iy  = rem / SW;
            int ix  = rem - iy * SW;
            int gy = 2 * ty0 + iy, gx = 2 * tx0 + ix;
            int ci = ci0 + c;
            float v = 0.f;
            if (gy < HIN && gx < WIN) {
                int frame = REMAP ? ((n % 16) * 10 + n / 16) : n;
                v = x[(((size_t)frame * CI + ci) * HIN + gy) * WIN + gx];
            }
            s_in[c][iy][ix] = v;
        }
        for (int idx = tid; idx < CICH * COT * 9; idx += NT) {
            int c   = idx / (COT * 9);
            int rem = idx - c * (COT * 9);
            int co  = rem / 9;
            int k   = rem - co * 9;
            s_w[c][co][k] = wgt[((cob + co) * CI + (ci0 + c)) * 9 + k];
        }
        __syncthreads();

        for (int c = 0; c < CICH; c++) {
            float p[3][3];
#pragma unroll
            for (int r = 0; r < 3; r++)
#pragma unroll
                for (int cc = 0; cc < 3; cc++)
                    p[r][cc] = s_in[c][2 * ly + r][2 * lx + cc];
#pragma unroll
            for (int co = 0; co < COT; co++) {
#pragma unroll
                for (int k = 0; k < 9; k++)
                    acc[co] = fmaf(p[k / 3][k % 3], s_w[c][co][k], acc[co]);
            }
        }
        __syncthreads();
    }

    const int oy = ty0 + ly, ox = tx0 + lx;
    if (oy < HO && ox < WO) {
#pragma unroll
        for (int co = 0; co < COT; co++) {
            float v = lrelu_f(acc[co] + bias[cob + co]);
            out[(((size_t)n * CO + cob + co) * HO + oy) * WO + ox] = v;
        }
    }
}

// ---------------------------------------------------------------------------
// Head: 3x3 conv, 8 -> 1 channels, 192x192.
// ---------------------------------------------------------------------------
__global__ void head_k(const float* __restrict__ x, const float* __restrict__ w,
                       const float* __restrict__ b, float* __restrict__ out)
{
    __shared__ float sw[72];
    __shared__ float sb;
    if (threadIdx.x < 72) sw[threadIdx.x] = w[threadIdx.x];
    if (threadIdx.x == 0) sb = b[0];
    __syncthreads();

    const int HW = 192 * 192;
    int idx = blockIdx.x * blockDim.x + threadIdx.x;
    if (idx >= 16 * HW) return;
    int n   = idx / HW;
    int rem = idx - n * HW;
    int y   = rem / 192;
    int xq  = rem - y * 192;

    float acc = sb;
#pragma unroll
    for (int ci = 0; ci < 8; ci++) {
        const float* xp = x + (size_t)(n * 8 + ci) * HW;
#pragma unroll
        for (int ky = 0; ky < 3; ky++) {
            int yy = y + ky - 1;
            if ((unsigned)yy >= 192u) continue;
#pragma unroll
            for (int kx = 0; kx < 3; kx++) {
                int xx = xq + kx - 1;
                if ((unsigned)xx >= 192u) continue;
                acc = fmaf(xp[yy * 192 + xx], sw[ci * 9 + ky * 3 + kx], acc);
            }
        }
    }
    out[idx] = acc;
}

// ---------------------------------------------------------------------------
// host
// ---------------------------------------------------------------------------
extern "C" void kernel_launch(void* const* d_in, const int* in_sizes, int n_in,
                              void* d_out, int out_size)
{
    const float* h1     = (const float*)d_in[0];
    const float* h2     = (const float*)d_in[1];
    const float* h3     = (const float*)d_in[2];
    const float* y_add  = (const float*)d_in[3];
    const float* enc_w1 = (const float*)d_in[4];
    const float* enc_b1 = (const float*)d_in[5];
    const float* enc_w2 = (const float*)d_in[6];
    const float* enc_b2 = (const float*)d_in[7];
    const float* enc_w3 = (const float*)d_in[8];
    const float* enc_b3 = (const float*)d_in[9];
    const float* g3wg   = (const float*)d_in[10];
    const float* g3bg   = (const float*)d_in[11];
    const float* g3wc   = (const float*)d_in[12];
    const float* g3bc   = (const float*)d_in[13];
    const float* g2wg   = (const float*)d_in[14];
    const float* g2bg   = (const float*)d_in[15];
    const float* g2wc   = (const float*)d_in[16];
    const float* g2bc   = (const float*)d_in[17];
    const float* g1wg   = (const float*)d_in[18];
    const float* g1bg   = (const float*)d_in[19];
    const float* g1wc   = (const float*)d_in[20];
    const float* g1bc   = (const float*)d_in[21];
    const float* s3w    = (const float*)d_in[22];
    const float* s3b    = (const float*)d_in[23];
    const float* s2w    = (const float*)d_in[24];
    const float* s2b    = (const float*)d_in[25];
    const float* s1w    = (const float*)d_in[26];
    const float* s1b    = (const float*)d_in[27];
    const float* hw     = (const float*)d_in[28];
    const float* hb     = (const float*)d_in[29];
    float* out = (float*)d_out;

    float *e1, *e2, *e3, *c3b, *c2b, *c1b, *gg3, *gg2, *gg1, *o3, *o2, *o1, *part;
    cudaGetSymbolAddress((void**)&e1, g_e1);
    cudaGetSymbolAddress((void**)&e2, g_e2);
    cudaGetSymbolAddress((void**)&e3, g_e3);
    cudaGetSymbolAddress((void**)&c3b, g_c3);
    cudaGetSymbolAddress((void**)&c2b, g_c2);
    cudaGetSymbolAddress((void**)&c1b, g_c1);
    cudaGetSymbolAddress((void**)&gg3, g_g3);
    cudaGetSymbolAddress((void**)&gg2, g_g2);
    cudaGetSymbolAddress((void**)&gg1, g_g1);
    cudaGetSymbolAddress((void**)&o3, g_o3);
    cudaGetSymbolAddress((void**)&o2, g_o2);
    cudaGetSymbolAddress((void**)&o1, g_o1);
    cudaGetSymbolAddress((void**)&part, g_part);

    const size_t SZ3 = (size_t)16 * 96 * 24 * 24;
    const size_t SZ2 = (size_t)16 * 64 * 48 * 48;
    const size_t SZ1 = (size_t)16 * 16 * 96 * 96;

    // -------- encoder over all 160 frames (transpose folded into enc1) -----
    conv3x3s2_k<1, 16, 192, true, 16, 16, 1, 16><<<dim3(36, 1, 160), 256>>>(
        y_add, enc_w1, enc_b1, e1);
    conv3x3s2_k<16, 64, 96, false, 16, 16, 8, 8><<<dim3(9, 8, 160), 256>>>(
        e1, enc_w2, enc_b2, e2);
    conv3x3s2_k<64, 96, 48, false, 16, 16, 8, 8><<<dim3(4, 12, 160), 256>>>(
        e2, enc_w3, enc_b3, e3);

    cudaMemcpyAsync(c3b, h3, SZ3 * sizeof(float), cudaMemcpyDeviceToDevice);
    cudaMemcpyAsync(c2b, h2, SZ2 * sizeof(float), cudaMemcpyDeviceToDevice);
    cudaMemcpyAsync(c1b, h1, SZ1 * sizeof(float), cudaMemcpyDeviceToDevice);

    for (int t = 0; t < 10; t++) {
        const float* x3 = e3 + (size_t)t * 16 * 96 * 24 * 24;
        float* c3c = c3b + (size_t)(t & 1) * SZ3;
        float* c3n = c3b + (size_t)((t + 1) & 1) * SZ3;
        float* c2c = c2b + (size_t)(t & 1) * SZ2;
        float* c2n = c2b + (size_t)((t + 1) & 1) * SZ2;
        float* c1c = c1b + (size_t)(t & 1) * SZ1;
        float* c1n = c1b + (size_t)((t + 1) & 1) * SZ1;

        // --- level 3 (24x24, 96 ch): R2 split-K kernels (measured faster) ---
        conv3x3_v2<96, 96, 192, 24, 24, 2, 1, 24, 24, 1, 8, 8, 4>
            <<<dim3(1, 24, 64), 144>>>(x3, c3c, nullptr, g3wg, g3bg, part);
        epi_k<192, 576, 4, 1><<<1728, 256>>>(part, g3bg, nullptr, nullptr, gg3);
        conv3x3_v2<96, 96, 96, 24, 24, 1, 2, 24, 24, 1, 8, 8, 4>
            <<<dim3(1, 12, 64), 144>>>(x3, c3c, gg3, g3wc, g3bc, part);
        epi_k<96, 576, 4, 2><<<864, 256>>>(part, g3bc, gg3, c3c, c3n);
        deconv_v2<96, 64, 24, 24, 24, 8, 4, 2, 0>
            <<<dim3(1, 16, 32), 144>>>(c3n, s3w, s3b, part);
        epi_k<64, 2304, 2, 0><<<2304, 256>>>(part, s3b, nullptr, nullptr, o3);

        // --- level 2 (48x48, 64 ch): R1 kernels (part of 24.8ms base) ---
        conv3x3_k<64, 64, 128, 48, 48, 2, 1, 16, 48, 8, 8>
            <<<dim3(3, 16, 16), 192>>>(o3, c2c, nullptr, g2wg, g2bg, gg2);
        conv3x3_k<64, 64, 64, 48, 48, 1, 2, 16, 48, 8, 8>
            <<<dim3(3, 8, 16), 192>>>(o3, c2c, gg2, g2wc, g2bc, c2n);
        deconv4x4_k<64, 16, 48, 16, 48, 8, 4>
            <<<dim3(3, 4, 16), 768>>>(c2n, s2w, s2b, o2);

        // --- level 1 (96x96, 16 ch): R1 kernels ---
        conv3x3_k<16, 16, 32, 96, 96, 2, 1, 16, 48, 8, 8>
            <<<dim3(12, 4, 16), 192>>>(o2, c1c, nullptr, g1wg, g1bg, gg1);
        conv3x3_k<16, 16, 16, 96, 96, 1, 2, 16, 48, 8, 8>
            <<<dim3(12, 2, 16), 192>>>(o2, c1c, gg1, g1wc, g1bc, c1n);
        deconv4x4_k<16, 8, 96, 16, 48, 8, 8>
            <<<dim3(12, 1, 16), 768>>>(c1n, s1w, s1b, o1);

        // --- head -> output slice [t] ---
        head_k<<<dim3((16 * 192 * 192 + 255) / 256), 256>>>(
            o1, hw, hb, out + (size_t)t * 16 * 192 * 192);
    }
}

// round 8
// speedup vs baseline: 3.2914x; 1.2624x over previous
#include <cuda_runtime.h>

// ---------------------------------------------------------------------------
// Forecaster_PONI round 8: R7 kernels unchanged; decoder levels pipelined
// across 3 streams (L3 spine / L2 / L1+head) inside the captured graph.
// ---------------------------------------------------------------------------

__device__ __forceinline__ float lrelu_f(float v) { return v > 0.f ? v : 0.2f * v; }
__device__ __forceinline__ float sigm_f(float v)  { return 1.f / (1.f + __expf(-v)); }

// ------------------------------ scratch buffers ----------------------------
__device__ float g_e1[160 * 16 * 96 * 96];
__device__ float g_e2[160 * 64 * 48 * 48];
__device__ float g_e3[160 * 96 * 24 * 24];
__device__ float g_c3[2][16 * 96 * 24 * 24];
__device__ float g_c2[2][16 * 64 * 48 * 48];
__device__ float g_c1[2][16 * 16 * 96 * 96];
__device__ float g_g3[16 * 192 * 24 * 24];
__device__ float g_g2[16 * 128 * 48 * 48];
__device__ float g_g1[16 * 32 * 96 * 96];
__device__ float g_o3[16 * 64 * 48 * 48];
__device__ float g_o2[16 * 16 * 96 * 96];
__device__ float g_o1[16 * 8 * 192 * 192];
__device__ float g_part[4 * 16 * 192 * 24 * 24 + 2 * 16 * 64 * 48 * 48];

static const int NB = 16;  // batch

// ---------------------------------------------------------------------------
// R2 conv3x3 (L3): PXR rows x 4 cols x COT channels; SPLIT>1 -> raw partials.
// ---------------------------------------------------------------------------
template<int C1, int C2, int CO, int H, int W, int ACT, int MODE,
         int TY, int TX, int PXR, int CICH, int COT, int SPLIT>
__global__ void __launch_bounds__((TY / PXR) * (TX / 4))
conv3x3_v2(const float* __restrict__ x1, const float* __restrict__ x2,
           const float* __restrict__ gates, const float* __restrict__ wgt,
           const float* __restrict__ bias, float* __restrict__ out)
{
    constexpr int CI  = C1 + C2;
    constexpr int CIP = CI / SPLIT;
    constexpr int SH  = TY + 2, SW = TX + 2, SWP = (SW + 3) & ~3;
    constexpr int NT  = (TY / PXR) * (TX / 4);
    constexpr int TILES_X = W / TX;

    __shared__ __align__(16) float s_in[CICH][SH][SWP];
    __shared__ __align__(16) float s_w[CICH][COT][12];

    const int zs  = blockIdx.z;
    const int n   = zs / SPLIT;
    const int sp  = zs % SPLIT;
    const int cob = blockIdx.y * COT;
    const int ty0 = (blockIdx.x / TILES_X) * TY;
    const int tx0 = (blockIdx.x % TILES_X) * TX;
    const int tid = threadIdx.x;
    const int lx  = tid % (TX / 4);
    const int ly  = tid / (TX / 4);

    float acc[COT][PXR][4];
#pragma unroll
    for (int c = 0; c < COT; c++)
#pragma unroll
        for (int r = 0; r < PXR; r++)
#pragma unroll
            for (int j = 0; j < 4; j++) acc[c][r][j] = 0.f;

    const int ci_base = sp * CIP;
    for (int ci0 = 0; ci0 < CIP; ci0 += CICH) {
        for (int idx = tid; idx < CICH * SH * SW; idx += NT) {
            int c   = idx / (SH * SW);
            int rem = idx - c * (SH * SW);
            int iy  = rem / SW;
            int ix  = rem - iy * SW;
            int gy = ty0 + iy - 1, gx = tx0 + ix - 1;
            int ci = ci_base + ci0 + c;
            float v = 0.f;
            if ((unsigned)gy < (unsigned)H && (unsigned)gx < (unsigned)W) {
                if (ci < C1) {
                    v = x1[(((size_t)n * C1 + ci) * H + gy) * W + gx];
                } else {
                    int c2 = ci - C1;
                    v = x2[(((size_t)n * C2 + c2) * H + gy) * W + gx];
                    if (MODE == 2)
                        v *= gates[(((size_t)n * 2 * C2 + C2 + c2) * H + gy) * W + gx];
                }
            }
            s_in[c][iy][ix] = v;
        }
        for (int idx = tid; idx < CICH * COT * 9; idx += NT) {
            int c   = idx / (COT * 9);
            int rem = idx - c * (COT * 9);
            int co  = rem / 9;
            int k   = rem - co * 9;
            s_w[c][co][k] = wgt[((cob + co) * CI + (ci_base + ci0 + c)) * 9 + k];
        }
        __syncthreads();

#pragma unroll
        for (int c = 0; c < CICH; c++) {
            float p[PXR + 2][6];
#pragma unroll
            for (int r = 0; r < PXR + 2; r++) {
                float4 q  = *(const float4*)&s_in[c][PXR * ly + r][4 * lx];
                float2 q2 = *(const float2*)&s_in[c][PXR * ly + r][4 * lx + 4];
                p[r][0] = q.x; p[r][1] = q.y; p[r][2] = q.z; p[r][3] = q.w;
                p[r][4] = q2.x; p[r][5] = q2.y;
            }
#pragma unroll
            for (int co = 0; co < COT; co++) {
                float4 w0 = *(const float4*)&s_w[c][co][0];
                float4 w1 = *(const float4*)&s_w[c][co][4];
                float  w8 = s_w[c][co][8];
                float wk[9] = {w0.x, w0.y, w0.z, w0.w, w1.x, w1.y, w1.z, w1.w, w8};
#pragma unroll
                for (int ky = 0; ky < 3; ky++)
#pragma unroll
                    for (int kx = 0; kx < 3; kx++)
#pragma unroll
                        for (int r = 0; r < PXR; r++)
#pragma unroll
                            for (int cc = 0; cc < 4; cc++)
                                acc[co][r][cc] = fmaf(p[r + ky][cc + kx],
                                                      wk[ky * 3 + kx],
                                                      acc[co][r][cc]);
            }
        }
        __syncthreads();
    }

    const int oy = ty0 + PXR * ly, ox = tx0 + 4 * lx;
    if (SPLIT > 1) {
#pragma unroll
        for (int co = 0; co < COT; co++)
#pragma unroll
            for (int r = 0; r < PXR; r++) {
                float4 v = {acc[co][r][0], acc[co][r][1], acc[co][r][2], acc[co][r][3]};
                *(float4*)&out[(((size_t)(sp * NB + n) * CO + cob + co) * H + oy + r) * W + ox] = v;
            }
    } else {
#pragma unroll
        for (int co = 0; co < COT; co++) {
            float bv = bias[cob + co];
#pragma unroll
            for (int r = 0; r < PXR; r++) {
                int y = oy + r;
                float v[4];
#pragma unroll
                for (int cc = 0; cc < 4; cc++) {
                    float t = acc[co][r][cc] + bv;
                    if (ACT == 1) t = lrelu_f(t);
                    if (ACT == 2) t = sigm_f(t);
                    v[cc] = t;
                }
                size_t off = (((size_t)n * CO + cob + co) * H + y) * W + ox;
                if (MODE == 2) {
                    float4 z4 = *(const float4*)&gates[(((size_t)n * 2 * CO + cob + co) * H + y) * W + ox];
                    float4 h4 = *(const float4*)&x2[off];
                    v[0] = (1.f - z4.x) * h4.x + z4.x * v[0];
                    v[1] = (1.f - z4.y) * h4.y + z4.y * v[1];
                    v[2] = (1.f - z4.z) * h4.z + z4.z * v[2];
                    v[3] = (1.f - z4.w) * h4.w + z4.w * v[3];
                }
                float4 o = {v[0], v[1], v[2], v[3]};
                *(float4*)&out[off] = o;
            }
        }
    }
}

// ---------------------------------------------------------------------------
// R2 deconv (L3): 2x2 input px -> 4x4 outputs; FUSE=0 -> raw partial write.
// ---------------------------------------------------------------------------
template<int CI, int CO, int HIN, int TY, int TX, int CICH, int COT, int SPLIT, int FUSE>
__global__ void __launch_bounds__((TY / 2) * (TX / 2))
deconv_v2(const float* __restrict__ x, const float* __restrict__ wgt,
          const float* __restrict__ bias, float* __restrict__ out)
{
    constexpr int WIN = HIN, HO = 2 * HIN, WO = 2 * HIN;
    constexpr int CIP = CI / SPLIT;
    constexpr int SH  = TY + 2, SW = TX + 2, SWP = (SW + 3) & ~3;
    constexpr int NT  = (TY / 2) * (TX / 2);
    constexpr int TILES_X = WIN / TX;

    __shared__ __align__(16) float s_in[CICH][SH][SWP];
    __shared__ __align__(16) float s_w[CICH][COT][16];

    const int zs  = blockIdx.z;
    const int n   = zs / SPLIT;
    const int sp  = zs % SPLIT;
    const int cob = blockIdx.y * COT;
    const int ty0 = (blockIdx.x / TILES_X) * TY;
    const int tx0 = (blockIdx.x % TILES_X) * TX;
    const int tid = threadIdx.x;
    const int lx  = tid % (TX / 2);
    const int ly  = tid / (TX / 2);

    float acc[COT][4][4];
#pragma unroll
    for (int c = 0; c < COT; c++)
#pragma unroll
        for (int u = 0; u < 4; u++)
#pragma unroll
            for (int v = 0; v < 4; v++) acc[c][u][v] = 0.f;

    const int ci_base = sp * CIP;
    for (int ci0 = 0; ci0 < CIP; ci0 += CICH) {
        for (int idx = tid; idx < CICH * SH * SW; idx += NT) {
            int c   = idx / (SH * SW);
            int rem = idx - c * (SH * SW);
            int iy  = rem / SW;
            int ix  = rem - iy * SW;
            int gy = ty0 + iy - 1, gx = tx0 + ix - 1;
            float v = 0.f;
            if ((unsigned)gy < (unsigned)HIN && (unsigned)gx < (unsigned)WIN)
                v = x[(((size_t)n * CI + (ci_base + ci0 + c)) * HIN + gy) * WIN + gx];
            s_in[c][iy][ix] = v;
        }
        for (int idx = tid; idx < CICH * COT * 16; idx += NT) {
            int c   = idx / (COT * 16);
            int rem = idx - c * (COT * 16);
            int co  = rem / 16;
            int k   = rem - co * 16;
            s_w[c][co][k] = wgt[((cob + co) * CI + (ci_base + ci0 + c)) * 16 + k];
        }
        __syncthreads();

#pragma unroll
        for (int c = 0; c < CICH; c++) {
            float p[4][4];
#pragma unroll
            for (int r = 0; r < 4; r++) {
                float2 a = *(const float2*)&s_in[c][2 * ly + r][2 * lx];
                float2 b = *(const float2*)&s_in[c][2 * ly + r][2 * lx + 2];
                p[r][0] = a.x; p[r][1] = a.y; p[r][2] = b.x; p[r][3] = b.y;
            }
#pragma unroll
            for (int co = 0; co < COT; co++) {
                float wk[16];
#pragma unroll
                for (int q = 0; q < 4; q++) {
                    float4 wv = *(const float4*)&s_w[c][co][4 * q];
                    wk[4 * q] = wv.x; wk[4 * q + 1] = wv.y;
                    wk[4 * q + 2] = wv.z; wk[4 * q + 3] = wv.w;
                }
#pragma unroll
                for (int u = 0; u < 4; u++)
#pragma unroll
                    for (int v = 0; v < 4; v++)
#pragma unroll
                        for (int a = 0; a < 2; a++)
#pragma unroll
                            for (int b = 0; b < 2; b++)
                                acc[co][u][v] = fmaf(
                                    p[(u >> 1) + (u & 1) + a][(v >> 1) + (v & 1) + b],
                                    wk[((u & 1) + 2 * a) * 4 + (v & 1) + 2 * b],
                                    acc[co][u][v]);
            }
        }
        __syncthreads();
    }

    const int orow0 = 2 * ty0 + 4 * ly;
    const int ocol0 = 2 * tx0 + 4 * lx;
#pragma unroll
    for (int co = 0; co < COT; co++) {
        float bv = FUSE ? bias[cob + co] : 0.f;
#pragma unroll
        for (int u = 0; u < 4; u++) {
            float4 v;
            if (FUSE) {
                v.x = lrelu_f(acc[co][u][0] + bv);
                v.y = lrelu_f(acc[co][u][1] + bv);
                v.z = lrelu_f(acc[co][u][2] + bv);
                v.w = lrelu_f(acc[co][u][3] + bv);
                *(float4*)&out[(((size_t)n * CO + cob + co) * HO + orow0 + u) * WO + ocol0] = v;
            } else {
                v.x = acc[co][u][0]; v.y = acc[co][u][1];
                v.z = acc[co][u][2]; v.w = acc[co][u][3];
                *(float4*)&out[(((size_t)(sp * NB + n) * CO + cob + co) * HO + orow0 + u) * WO + ocol0] = v;
            }
        }
    }
}

// ---------------------------------------------------------------------------
// Epilogue: sum SPLIT partials + bias; MODE 0 lrelu, 1 sigmoid, 2 GRU combine.
// ---------------------------------------------------------------------------
template<int CO, int HW, int SPLIT, int MODE>
__global__ void epi_k(const float* __restrict__ part, const float* __restrict__ bias,
                      const float* __restrict__ gates, const float* __restrict__ hprev,
                      float* __restrict__ out)
{
    constexpr size_t TOT = (size_t)NB * CO * HW;
    size_t i = ((size_t)blockIdx.x * blockDim.x + threadIdx.x) * 4;
    if (i >= TOT) return;
    int c   = (int)((i / HW) % CO);
    float4 s = *(const float4*)&part[i];
#pragma unroll
    for (int sp = 1; sp < SPLIT; sp++) {
        float4 q = *(const float4*)&part[(size_t)sp * TOT + i];
        s.x += q.x; s.y += q.y; s.z += q.z; s.w += q.w;
    }
    float bv = bias[c];
    s.x += bv; s.y += bv; s.z += bv; s.w += bv;
    if (MODE == 0) {
        s.x = lrelu_f(s.x); s.y = lrelu_f(s.y); s.z = lrelu_f(s.z); s.w = lrelu_f(s.w);
    } else if (MODE == 1) {
        s.x = sigm_f(s.x); s.y = sigm_f(s.y); s.z = sigm_f(s.z); s.w = sigm_f(s.w);
    } else {
        int n   = (int)(i / ((size_t)HW * CO));
        size_t pix = i % HW;
        float4 z = *(const float4*)&gates[((size_t)(n * 2 * CO + c)) * HW + pix];
        float4 h = *(const float4*)&hprev[i];
        s.x = (1.f - z.x) * h.x + z.x * lrelu_f(s.x);
        s.y = (1.f - z.y) * h.y + z.y * lrelu_f(s.y);
        s.z = (1.f - z.z) * h.z + z.z * lrelu_f(s.z);
        s.w = (1.f - z.w) * h.w + z.w * lrelu_f(s.w);
    }
    *(float4*)&out[i] = s;
}

// ---------------------------------------------------------------------------
// R1 conv3x3 (L2/L1): 2x2 px x COT per thread.
// ---------------------------------------------------------------------------
template<int C1, int C2, int CO, int H, int W, int ACT, int MODE,
         int TY, int TX, int CICH, int COT>
__global__ void __launch_bounds__((TY / 2) * (TX / 2))
conv3x3_k(const float* __restrict__ x1, const float* __restrict__ x2,
          const float* __restrict__ gates, const float* __restrict__ wgt,
          const float* __restrict__ bias, float* __restrict__ out)
{
    constexpr int CI = C1 + C2;
    constexpr int SH = TY + 2, SW = TX + 2;
    constexpr int NT = (TY / 2) * (TX / 2);
    constexpr int TILES_X = (W + TX - 1) / TX;
    __shared__ float s_in[CICH][SH][SW];
    __shared__ float s_w[CICH][COT][9];

    const int n   = blockIdx.z;
    const int cob = blockIdx.y * COT;
    const int ty0 = (blockIdx.x / TILES_X) * TY;
    const int tx0 = (blockIdx.x % TILES_X) * TX;
    const int tid = threadIdx.x;
    const int lx  = tid % (TX / 2);
    const int ly  = tid / (TX / 2);

    float acc[COT][2][2];
#pragma unroll
    for (int c = 0; c < COT; c++) {
        acc[c][0][0] = acc[c][0][1] = acc[c][1][0] = acc[c][1][1] = 0.f;
    }

    for (int ci0 = 0; ci0 < CI; ci0 += CICH) {
        for (int idx = tid; idx < CICH * SH * SW; idx += NT) {
            int c   = idx / (SH * SW);
            int rem = idx - c * (SH * SW);
            int iy  = rem / SW;
            int ix  = rem - iy * SW;
            int gy = ty0 + iy - 1, gx = tx0 + ix - 1;
            int ci = ci0 + c;
            float v = 0.f;
            if ((unsigned)gy < (unsigned)H && (unsigned)gx < (unsigned)W) {
                if (ci < C1) {
                    v = x1[(((size_t)n * C1 + ci) * H + gy) * W + gx];
                } else {
                    int c2 = ci - C1;
                    v = x2[(((size_t)n * C2 + c2) * H + gy) * W + gx];
                    if (MODE == 2)
                        v *= gates[(((size_t)n * 2 * C2 + C2 + c2) * H + gy) * W + gx];
                }
            }
            s_in[c][iy][ix] = v;
        }
        for (int idx = tid; idx < CICH * COT * 9; idx += NT) {
            int c   = idx / (COT * 9);
            int rem = idx - c * (COT * 9);
            int co  = rem / 9;
            int k   = rem - co * 9;
            s_w[c][co][k] = wgt[((cob + co) * CI + (ci0 + c)) * 9 + k];
        }
        __syncthreads();

        for (int c = 0; c < CICH; c++) {
            float p[4][4];
#pragma unroll
            for (int i = 0; i < 4; i++)
#pragma unroll
                for (int j = 0; j < 4; j++)
                    p[i][j] = s_in[c][2 * ly + i][2 * lx + j];
#pragma unroll
            for (int co = 0; co < COT; co++) {
#pragma unroll
                for (int ky = 0; ky < 3; ky++)
#pragma unroll
                    for (int kx = 0; kx < 3; kx++) {
                        float wv = s_w[c][co][ky * 3 + kx];
                        acc[co][0][0] = fmaf(p[ky][kx],         wv, acc[co][0][0]);
                        acc[co][0][1] = fmaf(p[ky][kx + 1],     wv, acc[co][0][1]);
                        acc[co][1][0] = fmaf(p[ky + 1][kx],     wv, acc[co][1][0]);
                        acc[co][1][1] = fmaf(p[ky + 1][kx + 1], wv, acc[co][1][1]);
                    }
            }
        }
        __syncthreads();
    }

    const int oy = ty0 + 2 * ly, ox = tx0 + 2 * lx;
#pragma unroll
    for (int co = 0; co < COT; co++) {
        float bv = bias[cob + co];
#pragma unroll
        for (int i = 0; i < 2; i++)
#pragma unroll
            for (int j = 0; j < 2; j++) {
                int y = oy + i, x = ox + j;
                if (y < H && x < W) {
                    float v = acc[co][i][j] + bv;
                    if (ACT == 1) v = lrelu_f(v);
                    if (ACT == 2) v = sigm_f(v);
                    size_t off = (((size_t)n * CO + cob + co) * H + y) * W + x;
                    if (MODE == 2) {
                        float z = gates[(((size_t)n * 2 * CO + cob + co) * H + y) * W + x];
                        float h = x2[off];
                        v = (1.f - z) * h + z * v;
                    }
                    out[off] = v;
                }
            }
    }
}

// ---------------------------------------------------------------------------
// R1 deconv (L2/L1): fused lrelu.
// ---------------------------------------------------------------------------
template<int CI, int CO, int HIN, int TY, int TX, int CICH, int COT>
__global__ void __launch_bounds__(TY * TX)
deconv4x4_k(const float* __restrict__ x, const float* __restrict__ wgt,
            const float* __restrict__ bias, float* __restrict__ out)
{
    constexpr int WIN = HIN, HO = 2 * HIN, WO = 2 * HIN;
    constexpr int SH = TY + 2, SW = TX + 2;
    constexpr int NT = TY * TX;
    constexpr int TILES_X = (WIN + TX - 1) / TX;
    __shared__ float s_in[CICH][SH][SW];
    __shared__ float s_w[CICH][COT][16];

    const int n   = blockIdx.z;
    const int cob = blockIdx.y * COT;
    const int ty0 = (blockIdx.x / TILES_X) * TY;
    const int tx0 = (blockIdx.x % TILES_X) * TX;
    const int tid = threadIdx.x;
    const int lx  = tid % TX;
    const int ly  = tid / TX;

    float acc[COT][2][2];
#pragma unroll
    for (int c = 0; c < COT; c++) {
        acc[c][0][0] = acc[c][0][1] = acc[c][1][0] = acc[c][1][1] = 0.f;
    }

    for (int ci0 = 0; ci0 < CI; ci0 += CICH) {
        for (int idx = tid; idx < CICH * SH * SW; idx += NT) {
            int c   = idx / (SH * SW);
            int rem = idx - c * (SH * SW);
            int iy  = rem / SW;
            int ix  = rem - iy * SW;
            int gy = ty0 + iy - 1, gx = tx0 + ix - 1;
            float v = 0.f;
            if ((unsigned)gy < (unsigned)HIN && (unsigned)gx < (unsigned)WIN)
                v = x[(((size_t)n * CI + (ci0 + c)) * HIN + gy) * WIN + gx];
            s_in[c][iy][ix] = v;
        }
        for (int idx = tid; idx < CICH * COT * 16; idx += NT) {
            int c   = idx / (COT * 16);
            int rem = idx - c * (COT * 16);
            int co  = rem / 16;
            int k   = rem - co * 16;
            s_w[c][co][k] = wgt[((cob + co) * CI + (ci0 + c)) * 16 + k];
        }
        __syncthreads();

        for (int c = 0; c < CICH; c++) {
            float p[3][3];
#pragma unroll
            for (int r = 0; r < 3; r++)
#pragma unroll
                for (int cc = 0; cc < 3; cc++)
                    p[r][cc] = s_in[c][ly + r][lx + cc];
#pragma unroll
            for (int co = 0; co < COT; co++) {
#pragma unroll
                for (int dy = 0; dy < 2; dy++)
#pragma unroll
                    for (int dx = 0; dx < 2; dx++)
#pragma unroll
                        for (int a = 0; a < 2; a++)
#pragma unroll
                            for (int b = 0; b < 2; b++)
                                acc[co][dy][dx] =
                                    fmaf(p[a + dy][b + dx],
                                         s_w[c][co][(dy + 2 * a) * 4 + (dx + 2 * b)],
                                         acc[co][dy][dx]);
            }
        }
        __syncthreads();
    }

    const int iy = ty0 + ly, ix = tx0 + lx;
    if (iy < HIN && ix < WIN) {
#pragma unroll
        for (int co = 0; co < COT; co++) {
            float bv = bias[cob + co];
#pragma unroll
            for (int dy = 0; dy < 2; dy++)
#pragma unroll
                for (int dx = 0; dx < 2; dx++) {
                    float v = lrelu_f(acc[co][dy][dx] + bv);
                    out[(((size_t)n * CO + cob + co) * HO + 2 * iy + dy) * WO + 2 * ix + dx] = v;
                }
        }
    }
}

// ---------------------------------------------------------------------------
// Encoder: 3x3 stride-2 SAME conv. REMAP folds [B,T]->[T,B] into enc1's read.
// ---------------------------------------------------------------------------
template<int CI, int CO, int HIN, bool REMAP, int TY, int TX, int CICH, int COT>
__global__ void __launch_bounds__(TY * TX)
conv3x3s2_k(const float* __restrict__ x, const float* __restrict__ wgt,
            const float* __restrict__ bias, float* __restrict__ out)
{
    constexpr int WIN = HIN, HO = HIN / 2, WO = HIN / 2;
    constexpr int SH = 2 * TY + 1, SW = 2 * TX + 1;
    constexpr int NT = TY * TX;
    constexpr int TILES_X = (WO + TX - 1) / TX;
    __shared__ float s_in[CICH][SH][SW];
    __shared__ float s_w[CICH][COT][9];

    const int n   = blockIdx.z;
    const int cob = blockIdx.y * COT;
    const int ty0 = (blockIdx.x / TILES_X) * TY;
    const int tx0 = (blockIdx.x % TILES_X) * TX;
    const int tid = threadIdx.x;
    const int lx  = tid % TX;
    const int ly  = tid / TX;

    float acc[COT];
#pragma unroll
    for (int c = 0; c < COT; c++) acc[c] = 0.f;

    for (int ci0 = 0; ci0 < CI; ci0 += CICH) {
        for (int idx = tid; idx < CICH * SH * SW; idx += NT) {
            int c   = idx / (SH * SW);
            int rem = idx - c * (SH * SW);
            int iy  = rem / SW;
            int ix  = rem - iy * SW;
            int gy = 2 * ty0 + iy, gx = 2 * tx0 + ix;
            int ci = ci0 + c;
            float v = 0.f;
            if (gy < HIN && gx < WIN) {
                int frame = REMAP ? ((n % 16) * 10 + n / 16) : n;
                v = x[(((size_t)frame * CI + ci) * HIN + gy) * WIN + gx];
            }
            s_in[c][iy][ix] = v;
        }
        for (int idx = tid; idx < CICH * COT * 9; idx += NT) {
            int c   = idx / (COT * 9);
            int rem = idx - c * (COT * 9);
            int co  = rem / 9;
            int k   = rem - co * 9;
            s_w[c][co][k] = wgt[((cob + co) * CI + (ci0 + c)) * 9 + k];
        }
        __syncthreads();

        for (int c = 0; c < CICH; c++) {
            float p[3][3];
#pragma unroll
            for (int r = 0; r < 3; r++)
#pragma unroll
                for (int cc = 0; cc < 3; cc++)
                    p[r][cc] = s_in[c][2 * ly + r][2 * lx + cc];
#pragma unroll
            for (int co = 0; co < COT; co++) {
#pragma unroll
                for (int k = 0; k < 9; k++)
                    acc[co] = fmaf(p[k / 3][k % 3], s_w[c][co][k], acc[co]);
            }
        }
        __syncthreads();
    }

    const int oy = ty0 + ly, ox = tx0 + lx;
    if (oy < HO && ox < WO) {
#pragma unroll
        for (int co = 0; co < COT; co++) {
            float v = lrelu_f(acc[co] + bias[cob + co]);
            out[(((size_t)n * CO + cob + co) * HO + oy) * WO + ox] = v;
        }
    }
}

// ---------------------------------------------------------------------------
// Head: 3x3 conv, 8 -> 1 channels, 192x192.
// ---------------------------------------------------------------------------
__global__ void head_k(const float* __restrict__ x, const float* __restrict__ w,
                       const float* __restrict__ b, float* __restrict__ out)
{
    __shared__ float sw[72];
    __shared__ float sb;
    if (threadIdx.x < 72) sw[threadIdx.x] = w[threadIdx.x];
    if (threadIdx.x == 0) sb = b[0];
    __syncthreads();

    const int HW = 192 * 192;
    int idx = blockIdx.x * blockDim.x + threadIdx.x;
    if (idx >= 16 * HW) return;
    int n   = idx / HW;
    int rem = idx - n * HW;
    int y   = rem / 192;
    int xq  = rem - y * 192;

    float acc = sb;
#pragma unroll
    for (int ci = 0; ci < 8; ci++) {
        const float* xp = x + (size_t)(n * 8 + ci) * HW;
#pragma unroll
        for (int ky = 0; ky < 3; ky++) {
            int yy = y + ky - 1;
            if ((unsigned)yy >= 192u) continue;
#pragma unroll
            for (int kx = 0; kx < 3; kx++) {
                int xx = xq + kx - 1;
                if ((unsigned)xx >= 192u) continue;
                acc = fmaf(xp[yy * 192 + xx], sw[ci * 9 + ky * 3 + kx], acc);
            }
        }
    }
    out[idx] = acc;
}

// ---------------------------------------------------------------------------
// stream/event context (host-side objects; created once, outside capture)
// ---------------------------------------------------------------------------
struct PipeCtx {
    cudaStream_t sA, sB, sC;
    cudaEvent_t  fork, joinA, joinB, joinC;
    cudaEvent_t  evA[10], evBo3[10], evB[10], evCo2[10];
};

static PipeCtx* get_ctx() {
    static PipeCtx* c = nullptr;
    if (!c) {
        c = new PipeCtx;
        cudaStreamCreateWithFlags(&c->sA, cudaStreamNonBlocking);
        cudaStreamCreateWithFlags(&c->sB, cudaStreamNonBlocking);
        cudaStreamCreateWithFlags(&c->sC, cudaStreamNonBlocking);
        cudaEventCreateWithFlags(&c->fork,  cudaEventDisableTiming);
        cudaEventCreateWithFlags(&c->joinA, cudaEventDisableTiming);
        cudaEventCreateWithFlags(&c->joinB, cudaEventDisableTiming);
        cudaEventCreateWithFlags(&c->joinC, cudaEventDisableTiming);
        for (int t = 0; t < 10; t++) {
            cudaEventCreateWithFlags(&c->evA[t],   cudaEventDisableTiming);
            cudaEventCreateWithFlags(&c->evBo3[t], cudaEventDisableTiming);
            cudaEventCreateWithFlags(&c->evB[t],   cudaEventDisableTiming);
            cudaEventCreateWithFlags(&c->evCo2[t], cudaEventDisableTiming);
        }
    }
    return c;
}

// ---------------------------------------------------------------------------
// host
// ---------------------------------------------------------------------------
extern "C" void kernel_launch(void* const* d_in, const int* in_sizes, int n_in,
                              void* d_out, int out_size)
{
    const float* h1     = (const float*)d_in[0];
    const float* h2     = (const float*)d_in[1];
    const float* h3     = (const float*)d_in[2];
    const float* y_add  = (const float*)d_in[3];
    const float* enc_w1 = (const float*)d_in[4];
    const float* enc_b1 = (const float*)d_in[5];
    const float* enc_w2 = (const float*)d_in[6];
    const float* enc_b2 = (const float*)d_in[7];
    const float* enc_w3 = (const float*)d_in[8];
    const float* enc_b3 = (const float*)d_in[9];
    const float* g3wg   = (const float*)d_in[10];
    const float* g3bg   = (const float*)d_in[11];
    const float* g3wc   = (const float*)d_in[12];
    const float* g3bc   = (const float*)d_in[13];
    const float* g2wg   = (const float*)d_in[14];
    const float* g2bg   = (const float*)d_in[15];
    const float* g2wc   = (const float*)d_in[16];
    const float* g2bc   = (const float*)d_in[17];
    const float* g1wg   = (const float*)d_in[18];
    const float* g1bg   = (const float*)d_in[19];
    const float* g1wc   = (const float*)d_in[20];
    const float* g1bc   = (const float*)d_in[21];
    const float* s3w    = (const float*)d_in[22];
    const float* s3b    = (const float*)d_in[23];
    const float* s2w    = (const float*)d_in[24];
    const float* s2b    = (const float*)d_in[25];
    const float* s1w    = (const float*)d_in[26];
    const float* s1b    = (const float*)d_in[27];
    const float* hw     = (const float*)d_in[28];
    const float* hb     = (const float*)d_in[29];
    float* out = (float*)d_out;

    float *e1, *e2, *e3, *c3b, *c2b, *c1b, *gg3, *gg2, *gg1, *o3, *o2, *o1, *part;
    cudaGetSymbolAddress((void**)&e1, g_e1);
    cudaGetSymbolAddress((void**)&e2, g_e2);
    cudaGetSymbolAddress((void**)&e3, g_e3);
    cudaGetSymbolAddress((void**)&c3b, g_c3);
    cudaGetSymbolAddress((void**)&c2b, g_c2);
    cudaGetSymbolAddress((void**)&c1b, g_c1);
    cudaGetSymbolAddress((void**)&gg3, g_g3);
    cudaGetSymbolAddress((void**)&gg2, g_g2);
    cudaGetSymbolAddress((void**)&gg1, g_g1);
    cudaGetSymbolAddress((void**)&o3, g_o3);
    cudaGetSymbolAddress((void**)&o2, g_o2);
    cudaGetSymbolAddress((void**)&o1, g_o1);
    cudaGetSymbolAddress((void**)&part, g_part);

    PipeCtx* c = get_ctx();
    cudaStream_t sA = c->sA, sB = c->sB, sC = c->sC;

    const size_t SZ3 = (size_t)16 * 96 * 24 * 24;
    const size_t SZ2 = (size_t)16 * 64 * 48 * 48;
    const size_t SZ1 = (size_t)16 * 16 * 96 * 96;

    // -------- encoder on the capture-origin stream --------------------------
    conv3x3s2_k<1, 16, 192, true, 16, 16, 1, 16><<<dim3(36, 1, 160), 256>>>(
        y_add, enc_w1, enc_b1, e1);
    conv3x3s2_k<16, 64, 96, false, 16, 16, 8, 8><<<dim3(9, 8, 160), 256>>>(
        e1, enc_w2, enc_b2, e2);
    conv3x3s2_k<64, 96, 48, false, 16, 16, 8, 8><<<dim3(4, 12, 160), 256>>>(
        e2, enc_w3, enc_b3, e3);

    cudaMemcpyAsync(c3b, h3, SZ3 * sizeof(float), cudaMemcpyDeviceToDevice);
    cudaMemcpyAsync(c2b, h2, SZ2 * sizeof(float), cudaMemcpyDeviceToDevice);
    cudaMemcpyAsync(c1b, h1, SZ1 * sizeof(float), cudaMemcpyDeviceToDevice);

    // -------- fork into 3 pipeline streams ----------------------------------
    cudaEventRecord(c->fork, 0);
    cudaStreamWaitEvent(sA, c->fork, 0);
    cudaStreamWaitEvent(sB, c->fork, 0);
    cudaStreamWaitEvent(sC, c->fork, 0);

    for (int t = 0; t < 10; t++) {
        const float* x3 = e3 + (size_t)t * 16 * 96 * 24 * 24;
        float* c3c = c3b + (size_t)(t & 1) * SZ3;
        float* c3n = c3b + (size_t)((t + 1) & 1) * SZ3;
        float* c2c = c2b + (size_t)(t & 1) * SZ2;
        float* c2n = c2b + (size_t)((t + 1) & 1) * SZ2;
        float* c1c = c1b + (size_t)(t & 1) * SZ1;
        float* c1n = c1b + (size_t)((t + 1) & 1) * SZ1;

        // ===== stream A: L3 spine (24x24, 96 ch) =====
        conv3x3_v2<96, 96, 192, 24, 24, 2, 1, 24, 24, 1, 8, 8, 4>
            <<<dim3(1, 24, 64), 144, 0, sA>>>(x3, c3c, nullptr, g3wg, g3bg, part);
        epi_k<192, 576, 4, 1><<<1728, 256, 0, sA>>>(part, g3bg, nullptr, nullptr, gg3);
        conv3x3_v2<96, 96, 96, 24, 24, 1, 2, 24, 24, 1, 8, 8, 4>
            <<<dim3(1, 12, 64), 144, 0, sA>>>(x3, c3c, gg3, g3wc, g3bc, part);
        epi_k<96, 576, 4, 2><<<864, 256, 0, sA>>>(part, g3bc, gg3, c3c, c3n);
        if (t > 0) cudaStreamWaitEvent(sA, c->evBo3[t - 1], 0);  // o3 readers done
        deconv_v2<96, 64, 24, 24, 24, 8, 4, 2, 0>
            <<<dim3(1, 16, 32), 144, 0, sA>>>(c3n, s3w, s3b, part);
        epi_k<64, 2304, 2, 0><<<2304, 256, 0, sA>>>(part, s3b, nullptr, nullptr, o3);
        cudaEventRecord(c->evA[t], sA);                          // o3(t) ready

        // ===== stream B: L2 (48x48, 64 ch) =====
        cudaStreamWaitEvent(sB, c->evA[t], 0);
        conv3x3_k<64, 64, 128, 48, 48, 2, 1, 16, 48, 8, 8>
            <<<dim3(3, 16, 16), 192, 0, sB>>>(o3, c2c, nullptr, g2wg, g2bg, gg2);
        conv3x3_k<64, 64, 64, 48, 48, 1, 2, 16, 48, 8, 8>
            <<<dim3(3, 8, 16), 192, 0, sB>>>(o3, c2c, gg2, g2wc, g2bc, c2n);
        cudaEventRecord(c->evBo3[t], sB);                        // done reading o3(t)
        if (t > 0) cudaStreamWaitEvent(sB, c->evCo2[t - 1], 0);  // o2 readers done
        deconv4x4_k<64, 16, 48, 16, 48, 8, 4>
            <<<dim3(3, 4, 16), 768, 0, sB>>>(c2n, s2w, s2b, o2);
        cudaEventRecord(c->evB[t], sB);                          // o2(t) ready

        // ===== stream C: L1 + head (96x96 / 192x192) =====
        cudaStreamWaitEvent(sC, c->evB[t], 0);
        conv3x3_k<16, 16, 32, 96, 96, 2, 1, 16, 48, 8, 8>
            <<<dim3(12, 4, 16), 192, 0, sC>>>(o2, c1c, nullptr, g1wg, g1bg, gg1);
        conv3x3_k<16, 16, 16, 96, 96, 1, 2, 16, 48, 8, 8>
            <<<dim3(12, 2, 16), 192, 0, sC>>>(o2, c1c, gg1, g1wc, g1bc, c1n);
        cudaEventRecord(c->evCo2[t], sC);                        // done reading o2(t)
        deconv4x4_k<16, 8, 96, 16, 48, 8, 8>
            <<<dim3(12, 1, 16), 768, 0, sC>>>(c1n, s1w, s1b, o1);
        head_k<<<dim3((16 * 192 * 192 + 255) / 256), 256, 0, sC>>>(
            o1, hw, hb, out + (size_t)t * 16 * 192 * 192);
    }

    // -------- join all streams back to the capture-origin stream ------------
    cudaEventRecord(c->joinA, sA);
    cudaEventRecord(c->joinB, sB);
    cudaEventRecord(c->joinC, sC);
    cudaStreamWaitEvent(0, c->joinA, 0);
    cudaStreamWaitEvent(0, c->joinB, 0);
    cudaStreamWaitEvent(0, c->joinC, 0);
}

// round 10
// speedup vs baseline: 3.3032x; 1.0036x over previous
#include <cuda_runtime.h>

// ---------------------------------------------------------------------------
// Forecaster_PONI round 10: R9's deeper pipeline re-mapped onto R8's exact
// 3-stream/44-event context (allocation-guard safe). Kernels unchanged.
//   sA: L3 GRU recurrence (gate3+cand3)
//   sB: deconv3 -> o3, then L2 GRU (gate2+cand2)
//   sC: deconv2 -> o2, L1 GRU, deconv1, head
// ---------------------------------------------------------------------------

__device__ __forceinline__ float lrelu_f(float v) { return v > 0.f ? v : 0.2f * v; }
__device__ __forceinline__ float sigm_f(float v)  { return 1.f / (1.f + __expf(-v)); }

// ------------------------------ scratch buffers ----------------------------
__device__ float g_e1[160 * 16 * 96 * 96];
__device__ float g_e2[160 * 64 * 48 * 48];
__device__ float g_e3[160 * 96 * 24 * 24];
__device__ float g_c3[2][16 * 96 * 24 * 24];
__device__ float g_c2[2][16 * 64 * 48 * 48];
__device__ float g_c1[2][16 * 16 * 96 * 96];
__device__ float g_g3[16 * 192 * 24 * 24];
__device__ float g_g2[16 * 128 * 48 * 48];
__device__ float g_g1[16 * 32 * 96 * 96];
__device__ float g_o3[16 * 64 * 48 * 48];
__device__ float g_o2[16 * 16 * 96 * 96];
__device__ float g_o1[16 * 8 * 192 * 192];
// partA: L3 gate/cand split-K partials (sA). partD: L3 deconv partials (sB).
__device__ float g_partA[4 * 16 * 192 * 24 * 24];
__device__ float g_partD[2 * 16 * 64 * 48 * 48];

static const int NB = 16;  // batch

// ---------------------------------------------------------------------------
// R2 conv3x3 (L3): PXR rows x 4 cols x COT channels; SPLIT>1 -> raw partials.
// ---------------------------------------------------------------------------
template<int C1, int C2, int CO, int H, int W, int ACT, int MODE,
         int TY, int TX, int PXR, int CICH, int COT, int SPLIT>
__global__ void __launch_bounds__((TY / PXR) * (TX / 4))
conv3x3_v2(const float* __restrict__ x1, const float* __restrict__ x2,
           const float* __restrict__ gates, const float* __restrict__ wgt,
           const float* __restrict__ bias, float* __restrict__ out)
{
    constexpr int CI  = C1 + C2;
    constexpr int CIP = CI / SPLIT;
    constexpr int SH  = TY + 2, SW = TX + 2, SWP = (SW + 3) & ~3;
    constexpr int NT  = (TY / PXR) * (TX / 4);
    constexpr int TILES_X = W / TX;

    __shared__ __align__(16) float s_in[CICH][SH][SWP];
    __shared__ __align__(16) float s_w[CICH][COT][12];

    const int zs  = blockIdx.z;
    const int n   = zs / SPLIT;
    const int sp  = zs % SPLIT;
    const int cob = blockIdx.y * COT;
    const int ty0 = (blockIdx.x / TILES_X) * TY;
    const int tx0 = (blockIdx.x % TILES_X) * TX;
    const int tid = threadIdx.x;
    const int lx  = tid % (TX / 4);
    const int ly  = tid / (TX / 4);

    float acc[COT][PXR][4];
#pragma unroll
    for (int c = 0; c < COT; c++)
#pragma unroll
        for (int r = 0; r < PXR; r++)
#pragma unroll
            for (int j = 0; j < 4; j++) acc[c][r][j] = 0.f;

    const int ci_base = sp * CIP;
    for (int ci0 = 0; ci0 < CIP; ci0 += CICH) {
        for (int idx = tid; idx < CICH * SH * SW; idx += NT) {
            int c   = idx / (SH * SW);
            int rem = idx - c * (SH * SW);
            int iy  = rem / SW;
            int ix  = rem - iy * SW;
            int gy = ty0 + iy - 1, gx = tx0 + ix - 1;
            int ci = ci_base + ci0 + c;
            float v = 0.f;
            if ((unsigned)gy < (unsigned)H && (unsigned)gx < (unsigned)W) {
                if (ci < C1) {
                    v = x1[(((size_t)n * C1 + ci) * H + gy) * W + gx];
                } else {
                    int c2 = ci - C1;
                    v = x2[(((size_t)n * C2 + c2) * H + gy) * W + gx];
                    if (MODE == 2)
                        v *= gates[(((size_t)n * 2 * C2 + C2 + c2) * H + gy) * W + gx];
                }
            }
            s_in[c][iy][ix] = v;
        }
        for (int idx = tid; idx < CICH * COT * 9; idx += NT) {
            int c   = idx / (COT * 9);
            int rem = idx - c * (COT * 9);
            int co  = rem / 9;
            int k   = rem - co * 9;
            s_w[c][co][k] = wgt[((cob + co) * CI + (ci_base + ci0 + c)) * 9 + k];
        }
        __syncthreads();

#pragma unroll
        for (int c = 0; c < CICH; c++) {
            float p[PXR + 2][6];
#pragma unroll
            for (int r = 0; r < PXR + 2; r++) {
                float4 q  = *(const float4*)&s_in[c][PXR * ly + r][4 * lx];
                float2 q2 = *(const float2*)&s_in[c][PXR * ly + r][4 * lx + 4];
                p[r][0] = q.x; p[r][1] = q.y; p[r][2] = q.z; p[r][3] = q.w;
                p[r][4] = q2.x; p[r][5] = q2.y;
            }
#pragma unroll
            for (int co = 0; co < COT; co++) {
                float4 w0 = *(const float4*)&s_w[c][co][0];
                float4 w1 = *(const float4*)&s_w[c][co][4];
                float  w8 = s_w[c][co][8];
                float wk[9] = {w0.x, w0.y, w0.z, w0.w, w1.x, w1.y, w1.z, w1.w, w8};
#pragma unroll
                for (int ky = 0; ky < 3; ky++)
#pragma unroll
                    for (int kx = 0; kx < 3; kx++)
#pragma unroll
                        for (int r = 0; r < PXR; r++)
#pragma unroll
                            for (int cc = 0; cc < 4; cc++)
                                acc[co][r][cc] = fmaf(p[r + ky][cc + kx],
                                                      wk[ky * 3 + kx],
                                                      acc[co][r][cc]);
            }
        }
        __syncthreads();
    }

    const int oy = ty0 + PXR * ly, ox = tx0 + 4 * lx;
    if (SPLIT > 1) {
#pragma unroll
        for (int co = 0; co < COT; co++)
#pragma unroll
            for (int r = 0; r < PXR; r++) {
                float4 v = {acc[co][r][0], acc[co][r][1], acc[co][r][2], acc[co][r][3]};
                *(float4*)&out[(((size_t)(sp * NB + n) * CO + cob + co) * H + oy + r) * W + ox] = v;
            }
    } else {
#pragma unroll
        for (int co = 0; co < COT; co++) {
            float bv = bias[cob + co];
#pragma unroll
            for (int r = 0; r < PXR; r++) {
                int y = oy + r;
                float v[4];
#pragma unroll
                for (int cc = 0; cc < 4; cc++) {
                    float t = acc[co][r][cc] + bv;
                    if (ACT == 1) t = lrelu_f(t);
                    if (ACT == 2) t = sigm_f(t);
                    v[cc] = t;
                }
                size_t off = (((size_t)n * CO + cob + co) * H + y) * W + ox;
                if (MODE == 2) {
                    float4 z4 = *(const float4*)&gates[(((size_t)n * 2 * CO + cob + co) * H + y) * W + ox];
                    float4 h4 = *(const float4*)&x2[off];
                    v[0] = (1.f - z4.x) * h4.x + z4.x * v[0];
                    v[1] = (1.f - z4.y) * h4.y + z4.y * v[1];
                    v[2] = (1.f - z4.z) * h4.z + z4.z * v[2];
                    v[3] = (1.f - z4.w) * h4.w + z4.w * v[3];
                }
                float4 o = {v[0], v[1], v[2], v[3]};
                *(float4*)&out[off] = o;
            }
        }
    }
}

// ---------------------------------------------------------------------------
// R2 deconv (L3): 2x2 input px -> 4x4 outputs; FUSE=0 -> raw partial write.
// ---------------------------------------------------------------------------
template<int CI, int CO, int HIN, int TY, int TX, int CICH, int COT, int SPLIT, int FUSE>
__global__ void __launch_bounds__((TY / 2) * (TX / 2))
deconv_v2(const float* __restrict__ x, const float* __restrict__ wgt,
          const float* __restrict__ bias, float* __restrict__ out)
{
    constexpr int WIN = HIN, HO = 2 * HIN, WO = 2 * HIN;
    constexpr int CIP = CI / SPLIT;
    constexpr int SH  = TY + 2, SW = TX + 2, SWP = (SW + 3) & ~3;
    constexpr int NT  = (TY / 2) * (TX / 2);
    constexpr int TILES_X = WIN / TX;

    __shared__ __align__(16) float s_in[CICH][SH][SWP];
    __shared__ __align__(16) float s_w[CICH][COT][16];

    const int zs  = blockIdx.z;
    const int n   = zs / SPLIT;
    const int sp  = zs % SPLIT;
    const int cob = blockIdx.y * COT;
    const int ty0 = (blockIdx.x / TILES_X) * TY;
    const int tx0 = (blockIdx.x % TILES_X) * TX;
    const int tid = threadIdx.x;
    const int lx  = tid % (TX / 2);
    const int ly  = tid / (TX / 2);

    float acc[COT][4][4];
#pragma unroll
    for (int c = 0; c < COT; c++)
#pragma unroll
        for (int u = 0; u < 4; u++)
#pragma unroll
            for (int v = 0; v < 4; v++) acc[c][u][v] = 0.f;

    const int ci_base = sp * CIP;
    for (int ci0 = 0; ci0 < CIP; ci0 += CICH) {
        for (int idx = tid; idx < CICH * SH * SW; idx += NT) {
            int c   = idx / (SH * SW);
            int rem = idx - c * (SH * SW);
            int iy  = rem / SW;
            int ix  = rem - iy * SW;
            int gy = ty0 + iy - 1, gx = tx0 + ix - 1;
            float v = 0.f;
            if ((unsigned)gy < (unsigned)HIN && (unsigned)gx < (unsigned)WIN)
                v = x[(((size_t)n * CI + (ci_base + ci0 + c)) * HIN + gy) * WIN + gx];
            s_in[c][iy][ix] = v;
        }
        for (int idx = tid; idx < CICH * COT * 16; idx += NT) {
            int c   = idx / (COT * 16);
            int rem = idx - c * (COT * 16);
            int co  = rem / 16;
            int k   = rem - co * 16;
            s_w[c][co][k] = wgt[((cob + co) * CI + (ci_base + ci0 + c)) * 16 + k];
        }
        __syncthreads();

#pragma unroll
        for (int c = 0; c < CICH; c++) {
            float p[4][4];
#pragma unroll
            for (int r = 0; r < 4; r++) {
                float2 a = *(const float2*)&s_in[c][2 * ly + r][2 * lx];
                float2 b = *(const float2*)&s_in[c][2 * ly + r][2 * lx + 2];
                p[r][0] = a.x; p[r][1] = a.y; p[r][2] = b.x; p[r][3] = b.y;
            }
#pragma unroll
            for (int co = 0; co < COT; co++) {
                float wk[16];
#pragma unroll
                for (int q = 0; q < 4; q++) {
                    float4 wv = *(const float4*)&s_w[c][co][4 * q];
                    wk[4 * q] = wv.x; wk[4 * q + 1] = wv.y;
                    wk[4 * q + 2] = wv.z; wk[4 * q + 3] = wv.w;
                }
#pragma unroll
                for (int u = 0; u < 4; u++)
#pragma unroll
                    for (int v = 0; v < 4; v++)
#pragma unroll
                        for (int a = 0; a < 2; a++)
#pragma unroll
                            for (int b = 0; b < 2; b++)
                                acc[co][u][v] = fmaf(
                                    p[(u >> 1) + (u & 1) + a][(v >> 1) + (v & 1) + b],
                                    wk[((u & 1) + 2 * a) * 4 + (v & 1) + 2 * b],
                                    acc[co][u][v]);
            }
        }
        __syncthreads();
    }

    const int orow0 = 2 * ty0 + 4 * ly;
    const int ocol0 = 2 * tx0 + 4 * lx;
#pragma unroll
    for (int co = 0; co < COT; co++) {
        float bv = FUSE ? bias[cob + co] : 0.f;
#pragma unroll
        for (int u = 0; u < 4; u++) {
            float4 v;
            if (FUSE) {
                v.x = lrelu_f(acc[co][u][0] + bv);
                v.y = lrelu_f(acc[co][u][1] + bv);
                v.z = lrelu_f(acc[co][u][2] + bv);
                v.w = lrelu_f(acc[co][u][3] + bv);
                *(float4*)&out[(((size_t)n * CO + cob + co) * HO + orow0 + u) * WO + ocol0] = v;
            } else {
                v.x = acc[co][u][0]; v.y = acc[co][u][1];
                v.z = acc[co][u][2]; v.w = acc[co][u][3];
                *(float4*)&out[(((size_t)(sp * NB + n) * CO + cob + co) * HO + orow0 + u) * WO + ocol0] = v;
            }
        }
    }
}

// ---------------------------------------------------------------------------
// Epilogue: sum SPLIT partials + bias; MODE 0 lrelu, 1 sigmoid, 2 GRU combine.
// ---------------------------------------------------------------------------
template<int CO, int HW, int SPLIT, int MODE>
__global__ void epi_k(const float* __restrict__ part, const float* __restrict__ bias,
                      const float* __restrict__ gates, const float* __restrict__ hprev,
                      float* __restrict__ out)
{
    constexpr size_t TOT = (size_t)NB * CO * HW;
    size_t i = ((size_t)blockIdx.x * blockDim.x + threadIdx.x) * 4;
    if (i >= TOT) return;
    int c   = (int)((i / HW) % CO);
    float4 s = *(const float4*)&part[i];
#pragma unroll
    for (int sp = 1; sp < SPLIT; sp++) {
        float4 q = *(const float4*)&part[(size_t)sp * TOT + i];
        s.x += q.x; s.y += q.y; s.z += q.z; s.w += q.w;
    }
    float bv = bias[c];
    s.x += bv; s.y += bv; s.z += bv; s.w += bv;
    if (MODE == 0) {
        s.x = lrelu_f(s.x); s.y = lrelu_f(s.y); s.z = lrelu_f(s.z); s.w = lrelu_f(s.w);
    } else if (MODE == 1) {
        s.x = sigm_f(s.x); s.y = sigm_f(s.y); s.z = sigm_f(s.z); s.w = sigm_f(s.w);
    } else {
        int n   = (int)(i / ((size_t)HW * CO));
        size_t pix = i % HW;
        float4 z = *(const float4*)&gates[((size_t)(n * 2 * CO + c)) * HW + pix];
        float4 h = *(const float4*)&hprev[i];
        s.x = (1.f - z.x) * h.x + z.x * lrelu_f(s.x);
        s.y = (1.f - z.y) * h.y + z.y * lrelu_f(s.y);
        s.z = (1.f - z.z) * h.z + z.z * lrelu_f(s.z);
        s.w = (1.f - z.w) * h.w + z.w * lrelu_f(s.w);
    }
    *(float4*)&out[i] = s;
}

// ---------------------------------------------------------------------------
// R1 conv3x3 (L2/L1): 2x2 px x COT per thread.
// ---------------------------------------------------------------------------
template<int C1, int C2, int CO, int H, int W, int ACT, int MODE,
         int TY, int TX, int CICH, int COT>
__global__ void __launch_bounds__((TY / 2) * (TX / 2))
conv3x3_k(const float* __restrict__ x1, const float* __restrict__ x2,
          const float* __restrict__ gates, const float* __restrict__ wgt,
          const float* __restrict__ bias, float* __restrict__ out)
{
    constexpr int CI = C1 + C2;
    constexpr int SH = TY + 2, SW = TX + 2;
    constexpr int NT = (TY / 2) * (TX / 2);
    constexpr int TILES_X = (W + TX - 1) / TX;
    __shared__ float s_in[CICH][SH][SW];
    __shared__ float s_w[CICH][COT][9];

    const int n   = blockIdx.z;
    const int cob = blockIdx.y * COT;
    const int ty0 = (blockIdx.x / TILES_X) * TY;
    const int tx0 = (blockIdx.x % TILES_X) * TX;
    const int tid = threadIdx.x;
    const int lx  = tid % (TX / 2);
    const int ly  = tid / (TX / 2);

    float acc[COT][2][2];
#pragma unroll
    for (int c = 0; c < COT; c++) {
        acc[c][0][0] = acc[c][0][1] = acc[c][1][0] = acc[c][1][1] = 0.f;
    }

    for (int ci0 = 0; ci0 < CI; ci0 += CICH) {
        for (int idx = tid; idx < CICH * SH * SW; idx += NT) {
            int c   = idx / (SH * SW);
            int rem = idx - c * (SH * SW);
            int iy  = rem / SW;
            int ix  = rem - iy * SW;
            int gy = ty0 + iy - 1, gx = tx0 + ix - 1;
            int ci = ci0 + c;
            float v = 0.f;
            if ((unsigned)gy < (unsigned)H && (unsigned)gx < (unsigned)W) {
                if (ci < C1) {
                    v = x1[(((size_t)n * C1 + ci) * H + gy) * W + gx];
                } else {
                    int c2 = ci - C1;
                    v = x2[(((size_t)n * C2 + c2) * H + gy) * W + gx];
                    if (MODE == 2)
                        v *= gates[(((size_t)n * 2 * C2 + C2 + c2) * H + gy) * W + gx];
                }
            }
            s_in[c][iy][ix] = v;
        }
        for (int idx = tid; idx < CICH * COT * 9; idx += NT) {
            int c   = idx / (COT * 9);
            int rem = idx - c * (COT * 9);
            int co  = rem / 9;
            int k   = rem - co * 9;
            s_w[c][co][k] = wgt[((cob + co) * CI + (ci0 + c)) * 9 + k];
        }
        __syncthreads();

        for (int c = 0; c < CICH; c++) {
            float p[4][4];
#pragma unroll
            for (int i = 0; i < 4; i++)
#pragma unroll
                for (int j = 0; j < 4; j++)
                    p[i][j] = s_in[c][2 * ly + i][2 * lx + j];
#pragma unroll
            for (int co = 0; co < COT; co++) {
#pragma unroll
                for (int ky = 0; ky < 3; ky++)
#pragma unroll
                    for (int kx = 0; kx < 3; kx++) {
                        float wv = s_w[c][co][ky * 3 + kx];
                        acc[co][0][0] = fmaf(p[ky][kx],         wv, acc[co][0][0]);
                        acc[co][0][1] = fmaf(p[ky][kx + 1],     wv, acc[co][0][1]);
                        acc[co][1][0] = fmaf(p[ky + 1][kx],     wv, acc[co][1][0]);
                        acc[co][1][1] = fmaf(p[ky + 1][kx + 1], wv, acc[co][1][1]);
                    }
            }
        }
        __syncthreads();
    }

    const int oy = ty0 + 2 * ly, ox = tx0 + 2 * lx;
#pragma unroll
    for (int co = 0; co < COT; co++) {
        float bv = bias[cob + co];
#pragma unroll
        for (int i = 0; i < 2; i++)
#pragma unroll
            for (int j = 0; j < 2; j++) {
                int y = oy + i, x = ox + j;
                if (y < H && x < W) {
                    float v = acc[co][i][j] + bv;
                    if (ACT == 1) v = lrelu_f(v);
                    if (ACT == 2) v = sigm_f(v);
                    size_t off = (((size_t)n * CO + cob + co) * H + y) * W + x;
                    if (MODE == 2) {
                        float z = gates[(((size_t)n * 2 * CO + cob + co) * H + y) * W + x];
                        float h = x2[off];
                        v = (1.f - z) * h + z * v;
                    }
                    out[off] = v;
                }
            }
    }
}

// ---------------------------------------------------------------------------
// R1 deconv (L2/L1): fused lrelu.
// ---------------------------------------------------------------------------
template<int CI, int CO, int HIN, int TY, int TX, int CICH, int COT>
__global__ void __launch_bounds__(TY * TX)
deconv4x4_k(const float* __restrict__ x, const float* __restrict__ wgt,
            const float* __restrict__ bias, float* __restrict__ out)
{
    constexpr int WIN = HIN, HO = 2 * HIN, WO = 2 * HIN;
    constexpr int SH = TY + 2, SW = TX + 2;
    constexpr int NT = TY * TX;
    constexpr int TILES_X = (WIN + TX - 1) / TX;
    __shared__ float s_in[CICH][SH][SW];
    __shared__ float s_w[CICH][COT][16];

    const int n   = blockIdx.z;
    const int cob = blockIdx.y * COT;
    const int ty0 = (blockIdx.x / TILES_X) * TY;
    const int tx0 = (blockIdx.x % TILES_X) * TX;
    const int tid = threadIdx.x;
    const int lx  = tid % TX;
    const int ly  = tid / TX;

    float acc[COT][2][2];
#pragma unroll
    for (int c = 0; c < COT; c++) {
        acc[c][0][0] = acc[c][0][1] = acc[c][1][0] = acc[c][1][1] = 0.f;
    }

    for (int ci0 = 0; ci0 < CI; ci0 += CICH) {
        for (int idx = tid; idx < CICH * SH * SW; idx += NT) {
            int c   = idx / (SH * SW);
            int rem = idx - c * (SH * SW);
            int iy  = rem / SW;
            int ix  = rem - iy * SW;
            int gy = ty0 + iy - 1, gx = tx0 + ix - 1;
            float v = 0.f;
            if ((unsigned)gy < (unsigned)HIN && (unsigned)gx < (unsigned)WIN)
                v = x[(((size_t)n * CI + (ci0 + c)) * HIN + gy) * WIN + gx];
            s_in[c][iy][ix] = v;
        }
        for (int idx = tid; idx < CICH * COT * 16; idx += NT) {
            int c   = idx / (COT * 16);
            int rem = idx - c * (COT * 16);
            int co  = rem / 16;
            int k   = rem - co * 16;
            s_w[c][co][k] = wgt[((cob + co) * CI + (ci0 + c)) * 16 + k];
        }
        __syncthreads();

        for (int c = 0; c < CICH; c++) {
            float p[3][3];
#pragma unroll
            for (int r = 0; r < 3; r++)
#pragma unroll
                for (int cc = 0; cc < 3; cc++)
                    p[r][cc] = s_in[c][ly + r][lx + cc];
#pragma unroll
            for (int co = 0; co < COT; co++) {
#pragma unroll
                for (int dy = 0; dy < 2; dy++)
#pragma unroll
                    for (int dx = 0; dx < 2; dx++)
#pragma unroll
                        for (int a = 0; a < 2; a++)
#pragma unroll
                            for (int b = 0; b < 2; b++)
                                acc[co][dy][dx] =
                                    fmaf(p[a + dy][b + dx],
                                         s_w[c][co][(dy + 2 * a) * 4 + (dx + 2 * b)],
                                         acc[co][dy][dx]);
            }
        }
        __syncthreads();
    }

    const int iy = ty0 + ly, ix = tx0 + lx;
    if (iy < HIN && ix < WIN) {
#pragma unroll
        for (int co = 0; co < COT; co++) {
            float bv = bias[cob + co];
#pragma unroll
            for (int dy = 0; dy < 2; dy++)
#pragma unroll
                for (int dx = 0; dx < 2; dx++) {
                    float v = lrelu_f(acc[co][dy][dx] + bv);
                    out[(((size_t)n * CO + cob + co) * HO + 2 * iy + dy) * WO + 2 * ix + dx] = v;
                }
        }
    }
}

// ---------------------------------------------------------------------------
// Encoder: 3x3 stride-2 SAME conv. REMAP folds [B,T]->[T,B] into enc1's read.
// ---------------------------------------------------------------------------
template<int CI, int CO, int HIN, bool REMAP, int TY, int TX, int CICH, int COT>
__global__ void __launch_bounds__(TY * TX)
conv3x3s2_k(const float* __restrict__ x, const float* __restrict__ wgt,
            const float* __restrict__ bias, float* __restrict__ out)
{
    constexpr int WIN = HIN, HO = HIN / 2, WO = HIN / 2;
    constexpr int SH = 2 * TY + 1, SW = 2 * TX + 1;
    constexpr int NT = TY * TX;
    constexpr int TILES_X = (WO + TX - 1) / TX;
    __shared__ float s_in[CICH][SH][SW];
    __shared__ float s_w[CICH][COT][9];

    const int n   = blockIdx.z;
    const int cob = blockIdx.y * COT;
    const int ty0 = (blockIdx.x / TILES_X) * TY;
    const int tx0 = (blockIdx.x % TILES_X) * TX;
    const int tid = threadIdx.x;
    const int lx  = tid % TX;
    const int ly  = tid / TX;

    float acc[COT];
#pragma unroll
    for (int c = 0; c < COT; c++) acc[c] = 0.f;

    for (int ci0 = 0; ci0 < CI; ci0 += CICH) {
        for (int idx = tid; idx < CICH * SH * SW; idx += NT) {
            int c   = idx / (SH * SW);
            int rem = idx - c * (SH * SW);
            int iy  = rem / SW;
            int ix  = rem - iy * SW;
            int gy = 2 * ty0 + iy, gx = 2 * tx0 + ix;
            int ci = ci0 + c;
            float v = 0.f;
            if (gy < HIN && gx < WIN) {
                int frame = REMAP ? ((n % 16) * 10 + n / 16) : n;
                v = x[(((size_t)frame * CI + ci) * HIN + gy) * WIN + gx];
            }
            s_in[c][iy][ix] = v;
        }
        for (int idx = tid; idx < CICH * COT * 9; idx += NT) {
            int c   = idx / (COT * 9);
            int rem = idx - c * (COT * 9);
            int co  = rem / 9;
            int k   = rem - co * 9;
            s_w[c][co][k] = wgt[((cob + co) * CI + (ci0 + c)) * 9 + k];
        }
        __syncthreads();

        for (int c = 0; c < CICH; c++) {
            float p[3][3];
#pragma unroll
            for (int r = 0; r < 3; r++)
#pragma unroll
                for (int cc = 0; cc < 3; cc++)
                    p[r][cc] = s_in[c][2 * ly + r][2 * lx + cc];
#pragma unroll
            for (int co = 0; co < COT; co++) {
#pragma unroll
                for (int k = 0; k < 9; k++)
                    acc[co] = fmaf(p[k / 3][k % 3], s_w[c][co][k], acc[co]);
            }
        }
        __syncthreads();
    }

    const int oy = ty0 + ly, ox = tx0 + lx;
    if (oy < HO && ox < WO) {
#pragma unroll
        for (int co = 0; co < COT; co++) {
            float v = lrelu_f(acc[co] + bias[cob + co]);
            out[(((size_t)n * CO + cob + co) * HO + oy) * WO + ox] = v;
        }
    }
}

// ---------------------------------------------------------------------------
// Head: 3x3 conv, 8 -> 1 channels, 192x192.
// ---------------------------------------------------------------------------
__global__ void head_k(const float* __restrict__ x, const float* __restrict__ w,
                       const float* __restrict__ b, float* __restrict__ out)
{
    __shared__ float sw[72];
    __shared__ float sb;
    if (threadIdx.x < 72) sw[threadIdx.x] = w[threadIdx.x];
    if (threadIdx.x == 0) sb = b[0];
    __syncthreads();

    const int HW = 192 * 192;
    int idx = blockIdx.x * blockDim.x + threadIdx.x;
    if (idx >= 16 * HW) return;
    int n   = idx / HW;
    int rem = idx - n * HW;
    int y   = rem / 192;
    int xq  = rem - y * 192;

    float acc = sb;
#pragma unroll
    for (int ci = 0; ci < 8; ci++) {
        const float* xp = x + (size_t)(n * 8 + ci) * HW;
#pragma unroll
        for (int ky = 0; ky < 3; ky++) {
            int yy = y + ky - 1;
            if ((unsigned)yy >= 192u) continue;
#pragma unroll
            for (int kx = 0; kx < 3; kx++) {
                int xx = xq + kx - 1;
                if ((unsigned)xx >= 192u) continue;
                acc = fmaf(xp[yy * 192 + xx], sw[ci * 9 + ky * 3 + kx], acc);
            }
        }
    }
    out[idx] = acc;
}

// ---------------------------------------------------------------------------
// stream/event context — IDENTICAL object count to the passing R8 context:
// 3 streams, 4 single events, 4 arrays of 10 events.
// ---------------------------------------------------------------------------
struct PipeCtx {
    cudaStream_t sA, sB, sC;
    cudaEvent_t  fork, jA, jB, jC;
    cudaEvent_t  eA[10];    // A: c3n(t) ready
    cudaEvent_t  eBc3[10];  // B: deconv3(t) done reading c3n(t)
    cudaEvent_t  eB[10];    // B: c2n(t) ready
    cudaEvent_t  eCc2[10];  // C: deconv2(t) done reading c2n(t)
};

static PipeCtx* get_ctx() {
    static PipeCtx* c = nullptr;
    if (!c) {
        c = new PipeCtx;
        cudaStreamCreateWithFlags(&c->sA, cudaStreamNonBlocking);
        cudaStreamCreateWithFlags(&c->sB, cudaStreamNonBlocking);
        cudaStreamCreateWithFlags(&c->sC, cudaStreamNonBlocking);
        cudaEventCreateWithFlags(&c->fork, cudaEventDisableTiming);
        cudaEventCreateWithFlags(&c->jA,   cudaEventDisableTiming);
        cudaEventCreateWithFlags(&c->jB,   cudaEventDisableTiming);
        cudaEventCreateWithFlags(&c->jC,   cudaEventDisableTiming);
        for (int t = 0; t < 10; t++) {
            cudaEventCreateWithFlags(&c->eA[t],   cudaEventDisableTiming);
            cudaEventCreateWithFlags(&c->eBc3[t], cudaEventDisableTiming);
            cudaEventCreateWithFlags(&c->eB[t],   cudaEventDisableTiming);
            cudaEventCreateWithFlags(&c->eCc2[t], cudaEventDisableTiming);
        }
    }
    return c;
}

// ---------------------------------------------------------------------------
// host
// ---------------------------------------------------------------------------
extern "C" void kernel_launch(void* const* d_in, const int* in_sizes, int n_in,
                              void* d_out, int out_size)
{
    const float* h1     = (const float*)d_in[0];
    const float* h2     = (const float*)d_in[1];
    const float* h3     = (const float*)d_in[2];
    const float* y_add  = (const float*)d_in[3];
    const float* enc_w1 = (const float*)d_in[4];
    const float* enc_b1 = (const float*)d_in[5];
    const float* enc_w2 = (const float*)d_in[6];
    const float* enc_b2 = (const float*)d_in[7];
    const float* enc_w3 = (const float*)d_in[8];
    const float* enc_b3 = (const float*)d_in[9];
    const float* g3wg   = (const float*)d_in[10];
    const float* g3bg   = (const float*)d_in[11];
    const float* g3wc   = (const float*)d_in[12];
    const float* g3bc   = (const float*)d_in[13];
    const float* g2wg   = (const float*)d_in[14];
    const float* g2bg   = (const float*)d_in[15];
    const float* g2wc   = (const float*)d_in[16];
    const float* g2bc   = (const float*)d_in[17];
    const float* g1wg   = (const float*)d_in[18];
    const float* g1bg   = (const float*)d_in[19];
    const float* g1wc   = (const float*)d_in[20];
    const float* g1bc   = (const float*)d_in[21];
    const float* s3w    = (const float*)d_in[22];
    const float* s3b    = (const float*)d_in[23];
    const float* s2w    = (const float*)d_in[24];
    const float* s2b    = (const float*)d_in[25];
    const float* s1w    = (const float*)d_in[26];
    const float* s1b    = (const float*)d_in[27];
    const float* hw     = (const float*)d_in[28];
    const float* hb     = (const float*)d_in[29];
    float* out = (float*)d_out;

    float *e1, *e2, *e3, *c3b, *c2b, *c1b, *gg3, *gg2, *gg1, *o3, *o2, *o1, *partA, *partD;
    cudaGetSymbolAddress((void**)&e1, g_e1);
    cudaGetSymbolAddress((void**)&e2, g_e2);
    cudaGetSymbolAddress((void**)&e3, g_e3);
    cudaGetSymbolAddress((void**)&c3b, g_c3);
    cudaGetSymbolAddress((void**)&c2b, g_c2);
    cudaGetSymbolAddress((void**)&c1b, g_c1);
    cudaGetSymbolAddress((void**)&gg3, g_g3);
    cudaGetSymbolAddress((void**)&gg2, g_g2);
    cudaGetSymbolAddress((void**)&gg1, g_g1);
    cudaGetSymbolAddress((void**)&o3, g_o3);
    cudaGetSymbolAddress((void**)&o2, g_o2);
    cudaGetSymbolAddress((void**)&o1, g_o1);
    cudaGetSymbolAddress((void**)&partA, g_partA);
    cudaGetSymbolAddress((void**)&partD, g_partD);

    PipeCtx* c = get_ctx();
    cudaStream_t sA = c->sA, sB = c->sB, sC = c->sC;

    const size_t SZ3 = (size_t)16 * 96 * 24 * 24;
    const size_t SZ2 = (size_t)16 * 64 * 48 * 48;
    const size_t SZ1 = (size_t)16 * 16 * 96 * 96;

    // -------- encoder on the capture-origin stream --------------------------
    conv3x3s2_k<1, 16, 192, true, 16, 16, 1, 16><<<dim3(36, 1, 160), 256>>>(
        y_add, enc_w1, enc_b1, e1);
    conv3x3s2_k<16, 64, 96, false, 16, 16, 8, 8><<<dim3(9, 8, 160), 256>>>(
        e1, enc_w2, enc_b2, e2);
    conv3x3s2_k<64, 96, 48, false, 16, 16, 8, 8><<<dim3(4, 12, 160), 256>>>(
        e2, enc_w3, enc_b3, e3);

    cudaMemcpyAsync(c3b, h3, SZ3 * sizeof(float), cudaMemcpyDeviceToDevice);
    cudaMemcpyAsync(c2b, h2, SZ2 * sizeof(float), cudaMemcpyDeviceToDevice);
    cudaMemcpyAsync(c1b, h1, SZ1 * sizeof(float), cudaMemcpyDeviceToDevice);

    // -------- fork into 3 pipeline streams ----------------------------------
    cudaEventRecord(c->fork, 0);
    cudaStreamWaitEvent(sA, c->fork, 0);
    cudaStreamWaitEvent(sB, c->fork, 0);
    cudaStreamWaitEvent(sC, c->fork, 0);

    for (int t = 0; t < 10; t++) {
        const float* x3 = e3 + (size_t)t * 16 * 96 * 24 * 24;
        float* c3c = c3b + (size_t)(t & 1) * SZ3;
        float* c3n = c3b + (size_t)((t + 1) & 1) * SZ3;
        float* c2c = c2b + (size_t)(t & 1) * SZ2;
        float* c2n = c2b + (size_t)((t + 1) & 1) * SZ2;
        float* c1c = c1b + (size_t)(t & 1) * SZ1;
        float* c1n = c1b + (size_t)((t + 1) & 1) * SZ1;

        // ===== stream A: L3 GRU recurrence only (gate3 + cand3) =====
        conv3x3_v2<96, 96, 192, 24, 24, 2, 1, 24, 24, 1, 8, 8, 4>
            <<<dim3(1, 24, 64), 144, 0, sA>>>(x3, c3c, nullptr, g3wg, g3bg, partA);
        epi_k<192, 576, 4, 1><<<1728, 256, 0, sA>>>(partA, g3bg, nullptr, nullptr, gg3);
        conv3x3_v2<96, 96, 96, 24, 24, 1, 2, 24, 24, 1, 8, 8, 4>
            <<<dim3(1, 12, 64), 144, 0, sA>>>(x3, c3c, gg3, g3wc, g3bc, partA);
        // c3n buffer was read by deconv3(t-2) on sB: wait before overwriting
        if (t >= 2) cudaStreamWaitEvent(sA, c->eBc3[t - 2], 0);
        epi_k<96, 576, 4, 2><<<864, 256, 0, sA>>>(partA, g3bc, gg3, c3c, c3n);
        cudaEventRecord(c->eA[t], sA);                           // c3n(t) ready

        // ===== stream B: deconv3 -> o3, then L2 GRU (gate2 + cand2) =====
        cudaStreamWaitEvent(sB, c->eA[t], 0);
        deconv_v2<96, 64, 24, 24, 24, 8, 4, 2, 0>
            <<<dim3(1, 16, 32), 144, 0, sB>>>(c3n, s3w, s3b, partD);
        cudaEventRecord(c->eBc3[t], sB);                         // done reading c3n(t)
        epi_k<64, 2304, 2, 0><<<2304, 256, 0, sB>>>(partD, s3b, nullptr, nullptr, o3);
        conv3x3_k<64, 64, 128, 48, 48, 2, 1, 16, 48, 8, 8>
            <<<dim3(3, 16, 16), 192, 0, sB>>>(o3, c2c, nullptr, g2wg, g2bg, gg2);
        // c2n buffer was read by deconv2(t-2) on sC: wait before cand2 writes it
        if (t >= 2) cudaStreamWaitEvent(sB, c->eCc2[t - 2], 0);
        conv3x3_k<64, 64, 64, 48, 48, 1, 2, 16, 48, 8, 8>
            <<<dim3(3, 8, 16), 192, 0, sB>>>(o3, c2c, gg2, g2wc, g2bc, c2n);
        cudaEventRecord(c->eB[t], sB);                           // c2n(t) ready

        // ===== stream C: deconv2 -> o2, L1 GRU, deconv1, head =====
        cudaStreamWaitEvent(sC, c->eB[t], 0);
        deconv4x4_k<64, 16, 48, 16, 48, 8, 4>
            <<<dim3(3, 4, 16), 768, 0, sC>>>(c2n, s2w, s2b, o2);
        cudaEventRecord(c->eCc2[t], sC);                         // done reading c2n(t)
        conv3x3_k<16, 16, 32, 96, 96, 2, 1, 16, 48, 8, 8>
            <<<dim3(12, 4, 16), 192, 0, sC>>>(o2, c1c, nullptr, g1wg, g1bg, gg1);
        conv3x3_k<16, 16, 16, 96, 96, 1, 2, 16, 48, 8, 8>
            <<<dim3(12, 2, 16), 192, 0, sC>>>(o2, c1c, gg1, g1wc, g1bc, c1n);
        deconv4x4_k<16, 8, 96, 16, 48, 8, 8>
            <<<dim3(12, 1, 16), 768, 0, sC>>>(c1n, s1w, s1b, o1);
        head_k<<<dim3((16 * 192 * 192 + 255) / 256), 256, 0, sC>>>(
            o1, hw, hb, out + (size_t)t * 16 * 192 * 192);
    }

    // -------- join all streams back to the capture-origin stream ------------
    cudaEventRecord(c->jA, sA);
    cudaEventRecord(c->jB, sB);
    cudaEventRecord(c->jC, sC);
    cudaStreamWaitEvent(0, c->jA, 0);
    cudaStreamWaitEvent(0, c->jB, 0);
    cudaStreamWaitEvent(0, c->jC, 0);
}